// round 7
// baseline (speedup 1.0000x reference)
#include <cuda_runtime.h>
#include <cuda_fp16.h>
#include <math.h>
#include <stdint.h>

#define BATCH   16
#define SEQ     17
#define NNODE   256
#define FDIM    64
#define LWIN    16
#define BP      256         // BATCH*LWIN
#define N1      512
#define OUTD    64
#define NTOT    (BP*N1)
#define SLOPE   0.01f

// ---------------- scratch ----------------------------------------------------
__device__ __half g_nfh [(size_t)BP*N1*FDIM];
__device__ __half g_w1h [(size_t)BP*N1*FDIM];
__device__ __half g_adjh[(size_t)BP*N1*N1];     // 134 MB
__device__ __half g_th  [(size_t)BP*N1*FDIM];
__device__ __half g_oph [(size_t)BP*N1*OUTD];
__device__ float  g_z1  [(size_t)BP*N1*FDIM];
__device__ float  g_partA[2][2048][128];        // per-CTA (tile*BP+batch) partial sum/sumsq
__device__ float  g_coef[2][2][64];
__device__ __half g_Wh  [128*64];               // theta (th0;th1) * a, half
__device__ float  g_cbuf[128];                  // theta @ d

// ---------------- helpers ----------------------------------------------------
__device__ __forceinline__ uint32_t sptr(const void* p) {
    return (uint32_t)__cvta_generic_to_shared(p);
}
__device__ __forceinline__ void cp16(uint32_t d, const void* s) {
    asm volatile("cp.async.cg.shared.global [%0],[%1],16;" :: "r"(d), "l"(s));
}
#define CP_COMMIT asm volatile("cp.async.commit_group;")
#define CP_WAIT0  asm volatile("cp.async.wait_group 0;")
#define CP_WAIT1  asm volatile("cp.async.wait_group 1;")

__device__ __forceinline__ void mma_f16(float c[4], unsigned a0, unsigned a1,
                                        unsigned a2, unsigned a3,
                                        unsigned b0, unsigned b1) {
    asm volatile(
        "mma.sync.aligned.m16n8k16.row.col.f32.f16.f16.f32 "
        "{%0,%1,%2,%3},{%4,%5,%6,%7},{%8,%9},{%0,%1,%2,%3};"
        : "+f"(c[0]), "+f"(c[1]), "+f"(c[2]), "+f"(c[3])
        : "r"(a0), "r"(a1), "r"(a2), "r"(a3), "r"(b0), "r"(b1));
}
__device__ __forceinline__ void ldsm4h(unsigned& r0, unsigned& r1, unsigned& r2, unsigned& r3,
                                       const __half* base, int row0, int k0, int stride) {
    const int lane = threadIdx.x & 31;
    uint32_t a = sptr(base + (row0 + (lane & 15)) * stride + k0 + ((lane >> 4) << 3));
    asm volatile("ldmatrix.sync.aligned.m8n8.x4.shared.b16 {%0,%1,%2,%3},[%4];"
                 : "=r"(r0), "=r"(r1), "=r"(r2), "=r"(r3) : "r"(a));
}
__device__ __forceinline__ void ldsm2h_n(unsigned& r0, unsigned& r1,
                                         const __half* base, int n0, int k0, int stride) {
    const int l4 = threadIdx.x & 15;
    uint32_t a = sptr(base + (n0 + (l4 & 7)) * stride + k0 + ((l4 >> 3) << 3));
    asm volatile("ldmatrix.sync.aligned.m8n8.x2.shared.b16 {%0,%1},[%2];"
                 : "=r"(r0), "=r"(r1) : "r"(a));
}
__device__ __forceinline__ void ldsm2h_t(unsigned& r0, unsigned& r1,
                                         const __half* base, int k0, int n0, int stride) {
    const int l4 = threadIdx.x & 15;
    uint32_t a = sptr(base + (k0 + l4) * stride + n0);
    asm volatile("ldmatrix.sync.aligned.m8n8.x2.trans.shared.b16 {%0,%1},[%2];"
                 : "=r"(r0), "=r"(r1) : "r"(a));
}

// ---------------- K1: nf = gather(X) @ w2^T + b2  (+ BN0 stat partials) -----
__global__ void __launch_bounds__(256) k_nf(const float* __restrict__ x,
                                            const float* __restrict__ w2,
                                            const float* __restrict__ b2) {
    __shared__ __align__(16) __half sh[2 * 64 * 72];   // xh | wh ; reused as fp32 opst
    __half* xh = sh;
    __half* wh = sh + 64 * 72;
    const int tile = blockIdx.x, batch = blockIdx.y, tid = threadIdx.x;
    const int b = batch / LWIN, l = batch % LWIN;

    for (int e = tid; e < 1024; e += 256) {
        const int row = e >> 4, c4 = e & 15;
        const int r = tile * 64 + row, m = r >> 8, n = r & 255;
        float4 xv = *(const float4*)(x + ((size_t)(b * SEQ + l + m) * NNODE + n) * FDIM + c4 * 4);
        *(__half2*)(xh + row * 72 + c4 * 4)     = __floats2half2_rn(xv.x, xv.y);
        *(__half2*)(xh + row * 72 + c4 * 4 + 2) = __floats2half2_rn(xv.z, xv.w);
        float4 wv = *(const float4*)(w2 + row * 64 + c4 * 4);
        *(__half2*)(wh + row * 72 + c4 * 4)     = __floats2half2_rn(wv.x, wv.y);
        *(__half2*)(wh + row * 72 + c4 * 4 + 2) = __floats2half2_rn(wv.z, wv.w);
    }
    __syncthreads();

    const int w = tid >> 5, lane = tid & 31;
    const int band = w >> 1, colg = w & 1;
    const int lq = lane >> 2, lr = lane & 3;
    float acc[4][4];
#pragma unroll
    for (int t = 0; t < 4; t++) { acc[t][0] = acc[t][1] = acc[t][2] = acc[t][3] = 0.f; }
#pragma unroll
    for (int ks = 0; ks < 4; ks++) {
        const int k0 = ks * 16;
        unsigned a0, a1, a2, a3; ldsm4h(a0, a1, a2, a3, xh, band * 16, k0, 72);
#pragma unroll
        for (int t = 0; t < 4; t++) {
            unsigned b0, b1; ldsm2h_n(b0, b1, wh, colg * 32 + t * 8, k0, 72);
            mma_f16(acc[t], a0, a1, a2, a3, b0, b1);
        }
    }
    __syncthreads();           // all ldsm reads complete -> safe to reuse sh
    float* opst = (float*)sh;  // 64x64 fp32 tile
    const int r0l = band * 16 + lq;
    const size_t ob = ((size_t)batch * N1 + tile * 64 + r0l) * 64;
#pragma unroll
    for (int t = 0; t < 4; t++) {
        const int c = colg * 32 + t * 8 + lr * 2;
        const float bb0 = __ldg(b2 + c), bb1 = __ldg(b2 + c + 1);
        const float v00 = acc[t][0] + bb0, v01 = acc[t][1] + bb1;
        const float v10 = acc[t][2] + bb0, v11 = acc[t][3] + bb1;
        *(__half2*)(g_nfh + ob + c) = __floats2half2_rn(v00, v01);
        *(__half2*)(g_nfh + ob + (size_t)8 * 64 + c) = __floats2half2_rn(v10, v11);
        opst[r0l * 64 + c] = v00; opst[r0l * 64 + c + 1] = v01;
        opst[(r0l + 8) * 64 + c] = v10; opst[(r0l + 8) * 64 + c + 1] = v11;
    }
    __syncthreads();
    if (tid < 64) {
        float s = 0.f, q = 0.f;
        for (int r = 0; r < 64; r++) { float v = opst[r * 64 + tid]; s += v; q += v * v; }
        g_partA[0][tile * BP + batch][tid] = s;
        g_partA[0][tile * BP + batch][tid + 64] = q;
    }
}

// ---------------- stat reduce: partials -> coef ------------------------------
__global__ void k_p2(const float* __restrict__ w, const float* __restrict__ bb, int which) {
    const int tid = threadIdx.x;           // 256
    const int c = tid & 63, g = tid >> 6;
    float s = 0.f, q = 0.f;
    for (int e = g * 512; e < g * 512 + 512; e++) {
        s += g_partA[which][e][c];
        q += g_partA[which][e][c + 64];
    }
    __shared__ float sm[256], qm[256];
    sm[tid] = s; qm[tid] = q;
    __syncthreads();
    if (tid < 64) {
        const float S = sm[tid] + sm[tid + 64] + sm[tid + 128] + sm[tid + 192];
        const float Q = qm[tid] + qm[tid + 64] + qm[tid + 128] + qm[tid + 192];
        const float mu  = S / (float)NTOT;
        const float var = Q / (float)NTOT - mu * mu;
        const float a   = w[tid] * rsqrtf(var + 1e-5f);
        g_coef[which][0][tid] = a;
        g_coef[which][1][tid] = bb[tid] - mu * a;
    }
}

// ---------------- K1b: theta fold, parallel (128 blocks x 64 thr) -----------
__global__ void k_prep(const float* __restrict__ th0w, const float* __restrict__ th1w) {
    const int n = blockIdx.x, k = threadIdx.x;
    const float* wr = (n < 64) ? (th0w + n * 64) : (th1w + (n - 64) * 64);
    const float wv = wr[k];
    g_Wh[n * 64 + k] = __float2half(wv * g_coef[0][0][k]);
    float c = wv * g_coef[0][1][k];
#pragma unroll
    for (int o = 16; o > 0; o >>= 1) c += __shfl_xor_sync(~0u, c, o);
    __shared__ float sc[2];
    if ((k & 31) == 0) sc[k >> 5] = c;
    __syncthreads();
    if (k == 0) g_cbuf[n] = sc[0] + sc[1];
}

// ---------------- K2: z1 = xb@th0^T ; w1 = xb@th1^T (prefolded) -------------
__global__ void __launch_bounds__(256) k_pre() {
    extern __shared__ char sraw[];
    __half* nfh  = (__half*)sraw;
    __half* Wh   = (__half*)(sraw + 9216);
    float*  cbuf = (float*)(sraw + 27648);
    const int tile = blockIdx.x, batch = blockIdx.y, tid = threadIdx.x;

    for (int e = tid; e < 512; e += 256) {
        const int row = e >> 3, c8 = e & 7;
        cp16(sptr(nfh + row * 72 + c8 * 8),
             g_nfh + ((size_t)batch * N1 + tile * 64 + row) * 64 + c8 * 8);
    }
    for (int e = tid; e < 1024; e += 256) {
        const int row = e >> 3, c8 = e & 7;
        cp16(sptr(Wh + row * 72 + c8 * 8), g_Wh + row * 64 + c8 * 8);
    }
    if (tid < 32) cp16(sptr(cbuf + tid * 4), g_cbuf + tid * 4);
    CP_COMMIT; CP_WAIT0;
    __syncthreads();

    const int w = tid >> 5, lane = tid & 31;
    const int band = w >> 1, colg = w & 1;
    const int lq = lane >> 2, lr = lane & 3;
    float acc[8][4];
#pragma unroll
    for (int t = 0; t < 8; t++) { acc[t][0] = acc[t][1] = acc[t][2] = acc[t][3] = 0.f; }
#pragma unroll
    for (int ks = 0; ks < 4; ks++) {
        const int k0 = ks * 16;
        unsigned a0, a1, a2, a3; ldsm4h(a0, a1, a2, a3, nfh, band * 16, k0, 72);
#pragma unroll
        for (int t = 0; t < 8; t++) {
            unsigned b0, b1; ldsm2h_n(b0, b1, Wh, colg * 64 + t * 8, k0, 72);
            mma_f16(acc[t], a0, a1, a2, a3, b0, b1);
        }
    }
    const size_t rbase = (size_t)batch * N1 + tile * 64 + band * 16 + lq;
#pragma unroll
    for (int t = 0; t < 8; t++) {
        const int n = colg * 64 + t * 8 + lr * 2;
        const float c0 = cbuf[n], c1 = cbuf[n + 1];
        if (colg == 0) {
            *(float2*)(g_z1 + rbase * 64 + n) = make_float2(acc[t][0] + c0, acc[t][1] + c1);
            *(float2*)(g_z1 + (rbase + 8) * 64 + n) = make_float2(acc[t][2] + c0, acc[t][3] + c1);
        } else {
            const int nn = n - 64;
            *(__half2*)(g_w1h + rbase * 64 + nn) = __floats2half2_rn(acc[t][0] + c0, acc[t][1] + c1);
            *(__half2*)(g_w1h + (rbase + 8) * 64 + nn) = __floats2half2_rn(acc[t][2] + c0, acc[t][3] + c1);
        }
    }
}

// ---------------- K3: adj (softmax, no-max) and t = z1 + adj@w1 -------------
__global__ void __launch_bounds__(512, 2) k_adj() {
    extern __shared__ char sraw[];
    __half* nf_s  = (__half*)sraw;            // reused as w1 buffer
    __half* adj_s = (__half*)(sraw + 73728);
    float*  reds  = (float*)(sraw + 107008);
    const int tile = blockIdx.x, batch = blockIdx.y, tid = threadIdx.x;

    const __half* nfg = g_nfh + (size_t)batch * N1 * 64;
    for (int e = tid; e < 4096; e += 512)
        cp16(sptr(nf_s + (e >> 3) * 72 + (e & 7) * 8), nfg + e * 8);
    CP_COMMIT; CP_WAIT0;
    __syncthreads();

    const int w = tid >> 5, lane = tid & 31;
    const int band = w >> 3, colg = w & 7;
    const int lq = lane >> 2, lr = lane & 3;
    const int rl0 = band * 16 + lq;
    const int rg0 = tile * 32 + rl0, rg1 = rg0 + 8;

    float acc[8][4];
#pragma unroll
    for (int t = 0; t < 8; t++) { acc[t][0] = acc[t][1] = acc[t][2] = acc[t][3] = 0.f; }
#pragma unroll
    for (int ks = 0; ks < 4; ks++) {
        const int k0 = ks * 16;
        unsigned a0, a1, a2, a3; ldsm4h(a0, a1, a2, a3, nf_s, tile * 32 + band * 16, k0, 72);
#pragma unroll
        for (int t = 0; t < 8; t++) {
            unsigned b0, b1; ldsm2h_n(b0, b1, nf_s, colg * 64 + t * 8, k0, 72);
            mma_f16(acc[t], a0, a1, a2, a3, b0, b1);
        }
    }
    __syncthreads();

    const __half* w1g = g_w1h + (size_t)batch * N1 * 64;
    for (int e = tid; e < 4096; e += 512)
        cp16(sptr(nf_s + (e >> 3) * 72 + (e & 7) * 8), w1g + e * 8);
    CP_COMMIT;

    float s0 = 0.f, s1 = 0.f;
#pragma unroll
    for (int t = 0; t < 8; t++) {
#pragma unroll
        for (int j = 0; j < 2; j++) {
            const int col = colg * 64 + t * 8 + lr * 2 + j;
            float v = acc[t][j];
            if (col == rg0) v -= 1e8f;
            v = v > 0.f ? v : SLOPE * v;
            float e0 = __expf(v); acc[t][j] = e0; s0 += e0;
            float u = acc[t][2 + j];
            if (col == rg1) u -= 1e8f;
            u = u > 0.f ? u : SLOPE * u;
            float e1 = __expf(u); acc[t][2 + j] = e1; s1 += e1;
        }
    }
    s0 += __shfl_xor_sync(~0u, s0, 1); s0 += __shfl_xor_sync(~0u, s0, 2);
    s1 += __shfl_xor_sync(~0u, s1, 1); s1 += __shfl_xor_sync(~0u, s1, 2);
    if (lr == 0) { reds[rl0 * 8 + colg] = s0; reds[(rl0 + 8) * 8 + colg] = s1; }
    __syncthreads();
    float t0 = 0.f, t1 = 0.f;
#pragma unroll
    for (int c = 0; c < 8; c++) { t0 += reds[rl0 * 8 + c]; t1 += reds[(rl0 + 8) * 8 + c]; }
    const float inv0 = 1.f / t0, inv1 = 1.f / t1;
    const float msk = ((tile >= 8) != (colg >= 4)) ? 0.7f : 1.0f;

#pragma unroll
    for (int t = 0; t < 8; t++) {
#pragma unroll
        for (int j = 0; j < 2; j++) {
            const int col = colg * 64 + t * 8 + lr * 2 + j;
            float v = acc[t][j] * inv0;     if (col == rg0) v += 1.f;
            adj_s[rl0 * 520 + col] = __float2half(v * msk);
            float u = acc[t][2 + j] * inv1; if (col == rg1) u += 1.f;
            adj_s[(rl0 + 8) * 520 + col] = __float2half(u * msk);
        }
    }
    CP_WAIT0;
    __syncthreads();

    {
        const size_t gb = ((size_t)batch * N1 + tile * 32) * N1;
        for (int e = tid; e < 2048; e += 512) {
            const int r = e >> 6, c8 = e & 63;
            *(uint4*)(g_adjh + gb + (size_t)r * N1 + c8 * 8) =
                *(const uint4*)(adj_s + r * 520 + c8 * 8);
        }
    }

    const int n0 = colg * 8;
    float va[4] = {0.f, 0.f, 0.f, 0.f}, vb[4] = {0.f, 0.f, 0.f, 0.f};
#pragma unroll 4
    for (int ks = 0; ks < 32; ks += 2) {
        int k0 = ks * 16;
        unsigned a0, a1, a2, a3; ldsm4h(a0, a1, a2, a3, adj_s, band * 16, k0, 520);
        unsigned b0, b1; ldsm2h_t(b0, b1, nf_s, k0, n0, 72);
        mma_f16(va, a0, a1, a2, a3, b0, b1);
        k0 += 16;
        unsigned c0, c1, c2, c3; ldsm4h(c0, c1, c2, c3, adj_s, band * 16, k0, 520);
        unsigned d0, d1; ldsm2h_t(d0, d1, nf_s, k0, n0, 72);
        mma_f16(vb, c0, c1, c2, c3, d0, d1);
    }
    const size_t rb = (size_t)batch * N1 + tile * 32 + band * 16 + lq;
    const int cA = n0 + lr * 2;
    float2 z0 = *(const float2*)(g_z1 + rb * 64 + cA);
    float2 z1v = *(const float2*)(g_z1 + (rb + 8) * 64 + cA);
    *(__half2*)(g_th + rb * 64 + cA) =
        __floats2half2_rn(va[0] + vb[0] + z0.x, va[1] + vb[1] + z0.y);
    *(__half2*)(g_th + (rb + 8) * 64 + cA) =
        __floats2half2_rn(va[2] + vb[2] + z1v.x, va[3] + vb[3] + z1v.y);
}

// ---------------- K4: op = adj @ t + bias (+ BN1 stat partials) --------------
__global__ void __launch_bounds__(512, 2) k_out(const float* __restrict__ th0b,
                                                const float* __restrict__ th1b) {
    extern __shared__ char sraw[];
    __half* t_s = (__half*)sraw;
    __half* cbA = (__half*)(sraw + 73728);
    __half* cbB = (__half*)(sraw + 91136);
    const int tile = blockIdx.x, batch = blockIdx.y, tid = threadIdx.x;

    const __half* tg = g_th + (size_t)batch * N1 * 64;
    const __half* ag = g_adjh + ((size_t)batch * N1 + tile * 64) * N1;
    for (int e = tid; e < 4096; e += 512)
        cp16(sptr(t_s + (e >> 3) * 72 + (e & 7) * 8), tg + e * 8);
    for (int e = tid; e < 1024; e += 512) {
        const int r = e >> 4, c8 = e & 15;
        cp16(sptr(cbA + r * 136 + c8 * 8), ag + (size_t)r * N1 + c8 * 8);
    }
    CP_COMMIT;

    const int w = tid >> 5, lane = tid & 31;
    const int band = w >> 2, colg = w & 3;
    const int lq = lane >> 2, lr = lane & 3;
    float acc[2][4];
#pragma unroll
    for (int t = 0; t < 2; t++) { acc[t][0] = acc[t][1] = acc[t][2] = acc[t][3] = 0.f; }

    for (int ch = 0; ch < 4; ch++) {
        __half* cb = (ch & 1) ? cbB : cbA;
        if (ch < 3) {
            __half* nb = (ch & 1) ? cbA : cbB;
            for (int e = tid; e < 1024; e += 512) {
                const int r = e >> 4, c8 = e & 15;
                cp16(sptr(nb + r * 136 + c8 * 8), ag + (size_t)r * N1 + (ch + 1) * 128 + c8 * 8);
            }
            CP_COMMIT; CP_WAIT1;
        } else {
            CP_WAIT0;
        }
        __syncthreads();
#pragma unroll
        for (int ks = 0; ks < 8; ks++) {
            const int k0 = ks * 16;
            unsigned a0, a1, a2, a3; ldsm4h(a0, a1, a2, a3, cb, band * 16, k0, 136);
#pragma unroll
            for (int nt = 0; nt < 2; nt++) {
                unsigned b0, b1; ldsm2h_t(b0, b1, t_s, ch * 128 + k0, colg * 16 + nt * 8, 72);
                mma_f16(acc[nt], a0, a1, a2, a3, b0, b1);
            }
        }
        __syncthreads();
    }
    // epilogue: write half op + fp32 stats tile (reuse cbA/cbB region)
    float* opst = (float*)cbA;     // 64x64 fp32 = 16KB (cbA+cbB span 34816B)
    const int r0l = band * 16 + lq;
    const size_t rb = (size_t)batch * N1 + tile * 64 + r0l;
#pragma unroll
    for (int nt = 0; nt < 2; nt++) {
        const int cA = colg * 16 + nt * 8 + lr * 2;
        const float bc0 = __ldg(th0b + cA) + __ldg(th1b + cA);
        const float bc1 = __ldg(th0b + cA + 1) + __ldg(th1b + cA + 1);
        const float v00 = acc[nt][0] + bc0, v01 = acc[nt][1] + bc1;
        const float v10 = acc[nt][2] + bc0, v11 = acc[nt][3] + bc1;
        *(__half2*)(g_oph + rb * 64 + cA) = __floats2half2_rn(v00, v01);
        *(__half2*)(g_oph + (rb + 8) * 64 + cA) = __floats2half2_rn(v10, v11);
        opst[r0l * 64 + cA] = v00; opst[r0l * 64 + cA + 1] = v01;
        opst[(r0l + 8) * 64 + cA] = v10; opst[(r0l + 8) * 64 + cA + 1] = v11;
    }
    __syncthreads();
    if (tid < 64) {
        float s = 0.f, q = 0.f;
        for (int r = 0; r < 64; r++) { float v = opst[r * 64 + tid]; s += v; q += v * v; }
        g_partA[1][tile * BP + batch][tid] = s;
        g_partA[1][tile * BP + batch][tid + 64] = q;
    }
}

// ---------------- K5: BN1 affine + leaky + mean pool (half2 reads) -----------
__global__ void k_final(float* __restrict__ out) {
    const int idx = blockIdx.x * 256 + threadIdx.x;   // 131072 threads, 2 ch each
    const int c2 = idx & 31;
    const int n = (idx >> 5) & 255;
    const int b = idx >> 13;
    const float a0 = g_coef[1][0][c2 * 2], a1 = g_coef[1][0][c2 * 2 + 1];
    const float d0 = g_coef[1][1][c2 * 2], d1 = g_coef[1][1][c2 * 2 + 1];
    float s0 = 0.f, s1 = 0.f;
#pragma unroll 2
    for (int l = 0; l < LWIN; l++)
#pragma unroll
        for (int m = 0; m < 2; m++) {
            __half2 h = *(const __half2*)(g_oph +
                (((size_t)(b * LWIN + l) * N1 + m * NNODE + n) << 6) + c2 * 2);
            float2 f = __half22float2(h);
            float v0 = a0 * f.x + d0; s0 += (v0 > 0.f) ? v0 : SLOPE * v0;
            float v1 = a1 * f.y + d1; s1 += (v1 > 0.f) ? v1 : SLOPE * v1;
        }
    *(float2*)(out + (((size_t)(b * NNODE + n)) << 6) + c2 * 2) =
        make_float2(s0 * (1.f / 32.f), s1 * (1.f / 32.f));
}

// ---------------- launch ------------------------------------------------------
extern "C" void kernel_launch(void* const* d_in, const int* in_sizes, int n_in,
                              void* d_out, int out_size) {
    const float* x    = (const float*)d_in[0];
    const float* w2   = (const float*)d_in[1];
    const float* b2   = (const float*)d_in[2];
    const float* bn0w = (const float*)d_in[3];
    const float* bn0b = (const float*)d_in[4];
    const float* th0w = (const float*)d_in[5];
    const float* th0b = (const float*)d_in[6];
    const float* th1w = (const float*)d_in[7];
    const float* th1b = (const float*)d_in[8];
    const float* bn1w = (const float*)d_in[9];
    const float* bn1b = (const float*)d_in[10];
    float* out = (float*)d_out;

    const int SMEM_PRE = 28160;
    const int SMEM_ADJ = 108032;
    const int SMEM_OUT = 108544;
    cudaFuncSetAttribute(k_pre, cudaFuncAttributeMaxDynamicSharedMemorySize, SMEM_PRE);
    cudaFuncSetAttribute(k_adj, cudaFuncAttributeMaxDynamicSharedMemorySize, SMEM_ADJ);
    cudaFuncSetAttribute(k_out, cudaFuncAttributeMaxDynamicSharedMemorySize, SMEM_OUT);

    k_nf<<<dim3(8, BP), 256>>>(x, w2, b2);
    k_p2<<<1, 256>>>(bn0w, bn0b, 0);
    k_prep<<<128, 64>>>(th0w, th1w);
    k_pre<<<dim3(8, BP), 256, SMEM_PRE>>>();
    k_adj<<<dim3(16, BP), 512, SMEM_ADJ>>>();
    k_out<<<dim3(8, BP), 512, SMEM_OUT>>>(th0b, th1b);
    k_p2<<<1, 256>>>(bn1w, bn1b, 1);
    k_final<<<512, 256>>>(out);
}

// round 8
// speedup vs baseline: 1.0981x; 1.0981x over previous
#include <cuda_runtime.h>
#include <cuda_fp16.h>
#include <math.h>
#include <stdint.h>

#define BATCH   16
#define SEQ     17
#define NNODE   256
#define FDIM    64
#define LWIN    16
#define BP      256         // BATCH*LWIN
#define N1      512
#define OUTD    64
#define NTOT    (BP*N1)
#define SLOPE   0.01f

// ---------------- scratch ----------------------------------------------------
__device__ __half g_nfh [(size_t)BP*N1*FDIM];
__device__ __half g_w1h [(size_t)BP*N1*FDIM];
__device__ __half g_adjh[(size_t)BP*N1*N1];     // 134 MB
__device__ __half g_th  [(size_t)BP*N1*FDIM];
__device__ __half g_oph [(size_t)BP*N1*OUTD];
__device__ __half g_z1h [(size_t)BP*N1*FDIM];
__device__ float  g_part[2][BP][128];
__device__ float  g_coef[2][2][64];
__device__ __half g_Wh  [128*64];               // theta (th0;th1) * a, half
__device__ float  g_cbuf[128];                  // theta @ d

// ---------------- helpers ----------------------------------------------------
__device__ __forceinline__ uint32_t sptr(const void* p) {
    return (uint32_t)__cvta_generic_to_shared(p);
}
__device__ __forceinline__ void cp16(uint32_t d, const void* s) {
    asm volatile("cp.async.cg.shared.global [%0],[%1],16;" :: "r"(d), "l"(s));
}
#define CP_COMMIT asm volatile("cp.async.commit_group;")
#define CP_WAIT0  asm volatile("cp.async.wait_group 0;")
#define CP_WAIT1  asm volatile("cp.async.wait_group 1;")

__device__ __forceinline__ void mma_f16(float c[4], unsigned a0, unsigned a1,
                                        unsigned a2, unsigned a3,
                                        unsigned b0, unsigned b1) {
    asm volatile(
        "mma.sync.aligned.m16n8k16.row.col.f32.f16.f16.f32 "
        "{%0,%1,%2,%3},{%4,%5,%6,%7},{%8,%9},{%0,%1,%2,%3};"
        : "+f"(c[0]), "+f"(c[1]), "+f"(c[2]), "+f"(c[3])
        : "r"(a0), "r"(a1), "r"(a2), "r"(a3), "r"(b0), "r"(b1));
}
__device__ __forceinline__ void ldsm4h(unsigned& r0, unsigned& r1, unsigned& r2, unsigned& r3,
                                       const __half* base, int row0, int k0, int stride) {
    const int lane = threadIdx.x & 31;
    uint32_t a = sptr(base + (row0 + (lane & 15)) * stride + k0 + ((lane >> 4) << 3));
    asm volatile("ldmatrix.sync.aligned.m8n8.x4.shared.b16 {%0,%1,%2,%3},[%4];"
                 : "=r"(r0), "=r"(r1), "=r"(r2), "=r"(r3) : "r"(a));
}
__device__ __forceinline__ void ldsm2h_n(unsigned& r0, unsigned& r1,
                                         const __half* base, int n0, int k0, int stride) {
    const int l4 = threadIdx.x & 15;
    uint32_t a = sptr(base + (n0 + (l4 & 7)) * stride + k0 + ((l4 >> 3) << 3));
    asm volatile("ldmatrix.sync.aligned.m8n8.x2.shared.b16 {%0,%1},[%2];"
                 : "=r"(r0), "=r"(r1) : "r"(a));
}
__device__ __forceinline__ void ldsm2h_t(unsigned& r0, unsigned& r1,
                                         const __half* base, int k0, int n0, int stride) {
    const int l4 = threadIdx.x & 15;
    uint32_t a = sptr(base + (k0 + l4) * stride + n0);
    asm volatile("ldmatrix.sync.aligned.m8n8.x2.trans.shared.b16 {%0,%1},[%2];"
                 : "=r"(r0), "=r"(r1) : "r"(a));
}

// ---------------- K1: nf = gather(X) @ w2^T + b2 ----------------------------
__global__ void __launch_bounds__(256) k_nf(const float* __restrict__ x,
                                            const float* __restrict__ w2,
                                            const float* __restrict__ b2) {
    __shared__ __half xh[64 * 72];
    __shared__ __half wh[64 * 72];
    const int tile = blockIdx.x, batch = blockIdx.y, tid = threadIdx.x;
    const int b = batch / LWIN, l = batch % LWIN;

    for (int e = tid; e < 1024; e += 256) {
        const int row = e >> 4, c4 = e & 15;
        const int r = tile * 64 + row, m = r >> 8, n = r & 255;
        float4 xv = *(const float4*)(x + ((size_t)(b * SEQ + l + m) * NNODE + n) * FDIM + c4 * 4);
        *(__half2*)(xh + row * 72 + c4 * 4)     = __floats2half2_rn(xv.x, xv.y);
        *(__half2*)(xh + row * 72 + c4 * 4 + 2) = __floats2half2_rn(xv.z, xv.w);
        float4 wv = *(const float4*)(w2 + row * 64 + c4 * 4);
        *(__half2*)(wh + row * 72 + c4 * 4)     = __floats2half2_rn(wv.x, wv.y);
        *(__half2*)(wh + row * 72 + c4 * 4 + 2) = __floats2half2_rn(wv.z, wv.w);
    }
    __syncthreads();

    const int w = tid >> 5, lane = tid & 31;
    const int band = w >> 1, colg = w & 1;
    const int lq = lane >> 2, lr = lane & 3;
    float acc[4][4];
#pragma unroll
    for (int t = 0; t < 4; t++) { acc[t][0] = acc[t][1] = acc[t][2] = acc[t][3] = 0.f; }
#pragma unroll
    for (int ks = 0; ks < 4; ks++) {
        const int k0 = ks * 16;
        unsigned a0, a1, a2, a3; ldsm4h(a0, a1, a2, a3, xh, band * 16, k0, 72);
#pragma unroll
        for (int t = 0; t < 4; t++) {
            unsigned b0, b1; ldsm2h_n(b0, b1, wh, colg * 32 + t * 8, k0, 72);
            mma_f16(acc[t], a0, a1, a2, a3, b0, b1);
        }
    }
    const size_t ob = ((size_t)batch * N1 + tile * 64 + band * 16 + lq) * 64;
#pragma unroll
    for (int t = 0; t < 4; t++) {
        const int c = colg * 32 + t * 8 + lr * 2;
        const float bb0 = __ldg(b2 + c), bb1 = __ldg(b2 + c + 1);
        *(__half2*)(g_nfh + ob + c) = __floats2half2_rn(acc[t][0] + bb0, acc[t][1] + bb1);
        *(__half2*)(g_nfh + ob + (size_t)8 * 64 + c) = __floats2half2_rn(acc[t][2] + bb0, acc[t][3] + bb1);
    }
}

// ---------------- BN stats (streaming, half sources) --------------------------
__global__ void k_stats_p1(int which) {
    const int batch = blockIdx.x, tid = threadIdx.x;
    const int c = tid & 63, rg = tid >> 6;
    const __half* p = ((which == 0) ? g_nfh : g_oph) + (size_t)batch * N1 * 64;
    float s = 0.f, q = 0.f;
    for (int r = rg * 128; r < rg * 128 + 128; r++) {
        float v = __half2float(p[(size_t)r * 64 + c]);
        s += v; q += v * v;
    }
    __shared__ float sm[256], qm[256];
    sm[tid] = s; qm[tid] = q;
    __syncthreads();
    if (tid < 64) {
        g_part[which][batch][tid]      = sm[tid] + sm[tid + 64] + sm[tid + 128] + sm[tid + 192];
        g_part[which][batch][tid + 64] = qm[tid] + qm[tid + 64] + qm[tid + 128] + qm[tid + 192];
    }
}
__global__ void k_stats_p2(const float* __restrict__ w, const float* __restrict__ bb, int which) {
    const int c = threadIdx.x;
    float s = 0.f, q = 0.f;
    for (int b2 = 0; b2 < BP; b2++) { s += g_part[which][b2][c]; q += g_part[which][b2][c + 64]; }
    const float mu  = s / (float)NTOT;
    const float var = q / (float)NTOT - mu * mu;
    const float a   = w[c] * rsqrtf(var + 1e-5f);
    g_coef[which][0][c] = a;
    g_coef[which][1][c] = bb[c] - mu * a;
}

// ---------------- K1b: theta fold, parallel (128 blocks x 64 thr) -----------
__global__ void k_prep(const float* __restrict__ th0w, const float* __restrict__ th1w) {
    const int n = blockIdx.x, k = threadIdx.x;
    const float* wr = (n < 64) ? (th0w + n * 64) : (th1w + (n - 64) * 64);
    const float wv = wr[k];
    g_Wh[n * 64 + k] = __float2half(wv * g_coef[0][0][k]);
    float c = wv * g_coef[0][1][k];
#pragma unroll
    for (int o = 16; o > 0; o >>= 1) c += __shfl_xor_sync(~0u, c, o);
    __shared__ float sc[2];
    if ((k & 31) == 0) sc[k >> 5] = c;
    __syncthreads();
    if (k == 0) g_cbuf[n] = sc[0] + sc[1];
}

// ---------------- K2: z1 = xb@th0^T ; w1 = xb@th1^T (prefolded) -------------
__global__ void __launch_bounds__(256) k_pre() {
    extern __shared__ char sraw[];
    __half* nfh  = (__half*)sraw;
    __half* Wh   = (__half*)(sraw + 9216);
    float*  cbuf = (float*)(sraw + 27648);
    const int tile = blockIdx.x, batch = blockIdx.y, tid = threadIdx.x;

    for (int e = tid; e < 512; e += 256) {
        const int row = e >> 3, c8 = e & 7;
        cp16(sptr(nfh + row * 72 + c8 * 8),
             g_nfh + ((size_t)batch * N1 + tile * 64 + row) * 64 + c8 * 8);
    }
    for (int e = tid; e < 1024; e += 256) {
        const int row = e >> 3, c8 = e & 7;
        cp16(sptr(Wh + row * 72 + c8 * 8), g_Wh + row * 64 + c8 * 8);
    }
    if (tid < 32) cp16(sptr(cbuf + tid * 4), g_cbuf + tid * 4);
    CP_COMMIT; CP_WAIT0;
    __syncthreads();

    const int w = tid >> 5, lane = tid & 31;
    const int band = w >> 1, colg = w & 1;
    const int lq = lane >> 2, lr = lane & 3;
    float acc[8][4];
#pragma unroll
    for (int t = 0; t < 8; t++) { acc[t][0] = acc[t][1] = acc[t][2] = acc[t][3] = 0.f; }
#pragma unroll
    for (int ks = 0; ks < 4; ks++) {
        const int k0 = ks * 16;
        unsigned a0, a1, a2, a3; ldsm4h(a0, a1, a2, a3, nfh, band * 16, k0, 72);
#pragma unroll
        for (int t = 0; t < 8; t++) {
            unsigned b0, b1; ldsm2h_n(b0, b1, Wh, colg * 64 + t * 8, k0, 72);
            mma_f16(acc[t], a0, a1, a2, a3, b0, b1);
        }
    }
    const size_t rbase = (size_t)batch * N1 + tile * 64 + band * 16 + lq;
#pragma unroll
    for (int t = 0; t < 8; t++) {
        const int n = colg * 64 + t * 8 + lr * 2;
        const float c0 = cbuf[n], c1 = cbuf[n + 1];
        if (colg == 0) {
            *(__half2*)(g_z1h + rbase * 64 + n) = __floats2half2_rn(acc[t][0] + c0, acc[t][1] + c1);
            *(__half2*)(g_z1h + (rbase + 8) * 64 + n) = __floats2half2_rn(acc[t][2] + c0, acc[t][3] + c1);
        } else {
            const int nn = n - 64;
            *(__half2*)(g_w1h + rbase * 64 + nn) = __floats2half2_rn(acc[t][0] + c0, acc[t][1] + c1);
            *(__half2*)(g_w1h + (rbase + 8) * 64 + nn) = __floats2half2_rn(acc[t][2] + c0, acc[t][3] + c1);
        }
    }
}

// ---------------- K3: adj (softmax, no-max) and t = z1 + adj@w1 -------------
__global__ void __launch_bounds__(512, 2) k_adj() {
    extern __shared__ char sraw[];
    __half* nf_s  = (__half*)sraw;            // reused as w1 buffer
    __half* adj_s = (__half*)(sraw + 73728);
    float*  reds  = (float*)(sraw + 107008);
    const int tile = blockIdx.x, batch = blockIdx.y, tid = threadIdx.x;

    const __half* nfg = g_nfh + (size_t)batch * N1 * 64;
    for (int e = tid; e < 4096; e += 512)
        cp16(sptr(nf_s + (e >> 3) * 72 + (e & 7) * 8), nfg + e * 8);
    CP_COMMIT; CP_WAIT0;
    __syncthreads();

    const int w = tid >> 5, lane = tid & 31;
    const int band = w >> 3, colg = w & 7;
    const int lq = lane >> 2, lr = lane & 3;
    const int rl0 = band * 16 + lq;
    const int rg0 = tile * 32 + rl0, rg1 = rg0 + 8;

    float acc[8][4];
#pragma unroll
    for (int t = 0; t < 8; t++) { acc[t][0] = acc[t][1] = acc[t][2] = acc[t][3] = 0.f; }
#pragma unroll
    for (int ks = 0; ks < 4; ks++) {
        const int k0 = ks * 16;
        unsigned a0, a1, a2, a3; ldsm4h(a0, a1, a2, a3, nf_s, tile * 32 + band * 16, k0, 72);
#pragma unroll
        for (int t = 0; t < 8; t++) {
            unsigned b0, b1; ldsm2h_n(b0, b1, nf_s, colg * 64 + t * 8, k0, 72);
            mma_f16(acc[t], a0, a1, a2, a3, b0, b1);
        }
    }
    __syncthreads();

    const __half* w1g = g_w1h + (size_t)batch * N1 * 64;
    for (int e = tid; e < 4096; e += 512)
        cp16(sptr(nf_s + (e >> 3) * 72 + (e & 7) * 8), w1g + e * 8);
    CP_COMMIT;

    float s0 = 0.f, s1 = 0.f;
#pragma unroll
    for (int t = 0; t < 8; t++) {
#pragma unroll
        for (int j = 0; j < 2; j++) {
            const int col = colg * 64 + t * 8 + lr * 2 + j;
            float v = acc[t][j];
            if (col == rg0) v -= 1e8f;
            v = v > 0.f ? v : SLOPE * v;
            float e0 = __expf(v); acc[t][j] = e0; s0 += e0;
            float u = acc[t][2 + j];
            if (col == rg1) u -= 1e8f;
            u = u > 0.f ? u : SLOPE * u;
            float e1 = __expf(u); acc[t][2 + j] = e1; s1 += e1;
        }
    }
    s0 += __shfl_xor_sync(~0u, s0, 1); s0 += __shfl_xor_sync(~0u, s0, 2);
    s1 += __shfl_xor_sync(~0u, s1, 1); s1 += __shfl_xor_sync(~0u, s1, 2);
    if (lr == 0) { reds[rl0 * 8 + colg] = s0; reds[(rl0 + 8) * 8 + colg] = s1; }
    __syncthreads();
    float t0 = 0.f, t1 = 0.f;
#pragma unroll
    for (int c = 0; c < 8; c++) { t0 += reds[rl0 * 8 + c]; t1 += reds[(rl0 + 8) * 8 + c]; }
    const float inv0 = 1.f / t0, inv1 = 1.f / t1;
    const float msk = ((tile >= 8) != (colg >= 4)) ? 0.7f : 1.0f;

#pragma unroll
    for (int t = 0; t < 8; t++) {
#pragma unroll
        for (int j = 0; j < 2; j++) {
            const int col = colg * 64 + t * 8 + lr * 2 + j;
            float v = acc[t][j] * inv0;     if (col == rg0) v += 1.f;
            adj_s[rl0 * 520 + col] = __float2half(v * msk);
            float u = acc[t][2 + j] * inv1; if (col == rg1) u += 1.f;
            adj_s[(rl0 + 8) * 520 + col] = __float2half(u * msk);
        }
    }
    CP_WAIT0;
    __syncthreads();

    {
        const size_t gb = ((size_t)batch * N1 + tile * 32) * N1;
        for (int e = tid; e < 2048; e += 512) {
            const int r = e >> 6, c8 = e & 63;
            *(uint4*)(g_adjh + gb + (size_t)r * N1 + c8 * 8) =
                *(const uint4*)(adj_s + r * 520 + c8 * 8);
        }
    }

    const int n0 = colg * 8;
    float va[4] = {0.f, 0.f, 0.f, 0.f}, vb[4] = {0.f, 0.f, 0.f, 0.f};
#pragma unroll 4
    for (int ks = 0; ks < 32; ks += 2) {
        int k0 = ks * 16;
        unsigned a0, a1, a2, a3; ldsm4h(a0, a1, a2, a3, adj_s, band * 16, k0, 520);
        unsigned b0, b1; ldsm2h_t(b0, b1, nf_s, k0, n0, 72);
        mma_f16(va, a0, a1, a2, a3, b0, b1);
        k0 += 16;
        unsigned c0, c1, c2, c3; ldsm4h(c0, c1, c2, c3, adj_s, band * 16, k0, 520);
        unsigned d0, d1; ldsm2h_t(d0, d1, nf_s, k0, n0, 72);
        mma_f16(vb, c0, c1, c2, c3, d0, d1);
    }
    const size_t rb = (size_t)batch * N1 + tile * 32 + band * 16 + lq;
    const int cA = n0 + lr * 2;
    float2 z0 = __half22float2(*(const __half2*)(g_z1h + rb * 64 + cA));
    float2 z1v = __half22float2(*(const __half2*)(g_z1h + (rb + 8) * 64 + cA));
    *(__half2*)(g_th + rb * 64 + cA) =
        __floats2half2_rn(va[0] + vb[0] + z0.x, va[1] + vb[1] + z0.y);
    *(__half2*)(g_th + (rb + 8) * 64 + cA) =
        __floats2half2_rn(va[2] + vb[2] + z1v.x, va[3] + vb[3] + z1v.y);
}

// ---------------- K4: op = adj @ t + (th0b+th1b), 64-row tiles --------------
__global__ void __launch_bounds__(512, 2) k_out(const float* __restrict__ th0b,
                                                const float* __restrict__ th1b) {
    extern __shared__ char sraw[];
    __half* t_s = (__half*)sraw;
    __half* cbA = (__half*)(sraw + 73728);
    __half* cbB = (__half*)(sraw + 91136);
    const int tile = blockIdx.x, batch = blockIdx.y, tid = threadIdx.x;

    const __half* tg = g_th + (size_t)batch * N1 * 64;
    const __half* ag = g_adjh + ((size_t)batch * N1 + tile * 64) * N1;
    for (int e = tid; e < 4096; e += 512)
        cp16(sptr(t_s + (e >> 3) * 72 + (e & 7) * 8), tg + e * 8);
    for (int e = tid; e < 1024; e += 512) {
        const int r = e >> 4, c8 = e & 15;
        cp16(sptr(cbA + r * 136 + c8 * 8), ag + (size_t)r * N1 + c8 * 8);
    }
    CP_COMMIT;

    const int w = tid >> 5, lane = tid & 31;
    const int band = w >> 2, colg = w & 3;
    const int lq = lane >> 2, lr = lane & 3;
    float acc[2][4];
#pragma unroll
    for (int t = 0; t < 2; t++) { acc[t][0] = acc[t][1] = acc[t][2] = acc[t][3] = 0.f; }

    for (int ch = 0; ch < 4; ch++) {
        __half* cb = (ch & 1) ? cbB : cbA;
        if (ch < 3) {
            __half* nb = (ch & 1) ? cbA : cbB;
            for (int e = tid; e < 1024; e += 512) {
                const int r = e >> 4, c8 = e & 15;
                cp16(sptr(nb + r * 136 + c8 * 8), ag + (size_t)r * N1 + (ch + 1) * 128 + c8 * 8);
            }
            CP_COMMIT; CP_WAIT1;
        } else {
            CP_WAIT0;
        }
        __syncthreads();
#pragma unroll
        for (int ks = 0; ks < 8; ks++) {
            const int k0 = ks * 16;
            unsigned a0, a1, a2, a3; ldsm4h(a0, a1, a2, a3, cb, band * 16, k0, 136);
#pragma unroll
            for (int nt = 0; nt < 2; nt++) {
                unsigned b0, b1; ldsm2h_t(b0, b1, t_s, ch * 128 + k0, colg * 16 + nt * 8, 72);
                mma_f16(acc[nt], a0, a1, a2, a3, b0, b1);
            }
        }
        __syncthreads();
    }
    const size_t rb = (size_t)batch * N1 + tile * 64 + band * 16 + lq;
#pragma unroll
    for (int nt = 0; nt < 2; nt++) {
        const int cA = colg * 16 + nt * 8 + lr * 2;
        const float bc0 = __ldg(th0b + cA) + __ldg(th1b + cA);
        const float bc1 = __ldg(th0b + cA + 1) + __ldg(th1b + cA + 1);
        *(__half2*)(g_oph + rb * 64 + cA) = __floats2half2_rn(acc[nt][0] + bc0, acc[nt][1] + bc1);
        *(__half2*)(g_oph + (rb + 8) * 64 + cA) = __floats2half2_rn(acc[nt][2] + bc0, acc[nt][3] + bc1);
    }
}

// ---------------- K5: BN1 affine + leaky + mean pool (half2 reads) -----------
__global__ void k_final(float* __restrict__ out) {
    const int idx = blockIdx.x * 256 + threadIdx.x;   // 131072 threads, 2 ch each
    const int c2 = idx & 31;
    const int n = (idx >> 5) & 255;
    const int b = idx >> 13;
    const float a0 = g_coef[1][0][c2 * 2], a1 = g_coef[1][0][c2 * 2 + 1];
    const float d0 = g_coef[1][1][c2 * 2], d1 = g_coef[1][1][c2 * 2 + 1];
    float s0 = 0.f, s1 = 0.f;
#pragma unroll 2
    for (int l = 0; l < LWIN; l++)
#pragma unroll
        for (int m = 0; m < 2; m++) {
            __half2 h = *(const __half2*)(g_oph +
                (((size_t)(b * LWIN + l) * N1 + m * NNODE + n) << 6) + c2 * 2);
            float2 f = __half22float2(h);
            float v0 = a0 * f.x + d0; s0 += (v0 > 0.f) ? v0 : SLOPE * v0;
            float v1 = a1 * f.y + d1; s1 += (v1 > 0.f) ? v1 : SLOPE * v1;
        }
    *(float2*)(out + (((size_t)(b * NNODE + n)) << 6) + c2 * 2) =
        make_float2(s0 * (1.f / 32.f), s1 * (1.f / 32.f));
}

// ---------------- launch ------------------------------------------------------
extern "C" void kernel_launch(void* const* d_in, const int* in_sizes, int n_in,
                              void* d_out, int out_size) {
    const float* x    = (const float*)d_in[0];
    const float* w2   = (const float*)d_in[1];
    const float* b2   = (const float*)d_in[2];
    const float* bn0w = (const float*)d_in[3];
    const float* bn0b = (const float*)d_in[4];
    const float* th0w = (const float*)d_in[5];
    const float* th0b = (const float*)d_in[6];
    const float* th1w = (const float*)d_in[7];
    const float* th1b = (const float*)d_in[8];
    const float* bn1w = (const float*)d_in[9];
    const float* bn1b = (const float*)d_in[10];
    float* out = (float*)d_out;

    const int SMEM_PRE = 28160;
    const int SMEM_ADJ = 108032;
    const int SMEM_OUT = 108544;
    cudaFuncSetAttribute(k_pre, cudaFuncAttributeMaxDynamicSharedMemorySize, SMEM_PRE);
    cudaFuncSetAttribute(k_adj, cudaFuncAttributeMaxDynamicSharedMemorySize, SMEM_ADJ);
    cudaFuncSetAttribute(k_out, cudaFuncAttributeMaxDynamicSharedMemorySize, SMEM_OUT);

    k_nf<<<dim3(8, BP), 256>>>(x, w2, b2);
    k_stats_p1<<<BP, 256>>>(0);
    k_stats_p2<<<1, 64>>>(bn0w, bn0b, 0);
    k_prep<<<128, 64>>>(th0w, th1w);
    k_pre<<<dim3(8, BP), 256, SMEM_PRE>>>();
    k_adj<<<dim3(16, BP), 512, SMEM_ADJ>>>();
    k_out<<<dim3(8, BP), 512, SMEM_OUT>>>(th0b, th1b);
    k_stats_p1<<<BP, 256>>>(1);
    k_stats_p2<<<1, 64>>>(bn1w, bn1b, 1);
    k_final<<<512, 256>>>(out);
}

// round 9
// speedup vs baseline: 1.1181x; 1.0182x over previous
#include <cuda_runtime.h>
#include <cuda_fp16.h>
#include <math.h>
#include <stdint.h>

#define BATCH   16
#define SEQ     17
#define NNODE   256
#define FDIM    64
#define LWIN    16
#define BP      256         // BATCH*LWIN
#define N1      512
#define OUTD    64
#define NTOT    (BP*N1)
#define SLOPE   0.01f

// ---------------- scratch ----------------------------------------------------
__device__ __half g_nfh [(size_t)BP*N1*FDIM];
__device__ __half g_w1h [(size_t)BP*N1*FDIM];
__device__ __half g_adjh[(size_t)BP*N1*N1];     // 134 MB
__device__ __half g_th  [(size_t)BP*N1*FDIM];
__device__ __half g_oph [(size_t)BP*N1*OUTD];
__device__ float  g_part[2][BP][128];
__device__ float  g_coef[2][2][64];
__device__ __half g_Wh  [128*64];               // rows 0-63: th0*a ; 64-127: th1*a
__device__ float  g_cbuf[128];                  // theta @ d

// ---------------- helpers ----------------------------------------------------
__device__ __forceinline__ uint32_t sptr(const void* p) {
    return (uint32_t)__cvta_generic_to_shared(p);
}
__device__ __forceinline__ void cp16(uint32_t d, const void* s) {
    asm volatile("cp.async.cg.shared.global [%0],[%1],16;" :: "r"(d), "l"(s));
}
#define CP_COMMIT asm volatile("cp.async.commit_group;")
#define CP_WAIT0  asm volatile("cp.async.wait_group 0;")
#define CP_WAIT1  asm volatile("cp.async.wait_group 1;")

__device__ __forceinline__ void mma_f16(float c[4], unsigned a0, unsigned a1,
                                        unsigned a2, unsigned a3,
                                        unsigned b0, unsigned b1) {
    asm volatile(
        "mma.sync.aligned.m16n8k16.row.col.f32.f16.f16.f32 "
        "{%0,%1,%2,%3},{%4,%5,%6,%7},{%8,%9},{%0,%1,%2,%3};"
        : "+f"(c[0]), "+f"(c[1]), "+f"(c[2]), "+f"(c[3])
        : "r"(a0), "r"(a1), "r"(a2), "r"(a3), "r"(b0), "r"(b1));
}
// A-fragment (16x16), row-major [m][k]
__device__ __forceinline__ void ldsm4h(unsigned& r0, unsigned& r1, unsigned& r2, unsigned& r3,
                                       const __half* base, int row0, int k0, int stride) {
    const int lane = threadIdx.x & 31;
    uint32_t a = sptr(base + (row0 + (lane & 15)) * stride + k0 + ((lane >> 4) << 3));
    asm volatile("ldmatrix.sync.aligned.m8n8.x4.shared.b16 {%0,%1,%2,%3},[%4];"
                 : "=r"(r0), "=r"(r1), "=r"(r2), "=r"(r3) : "r"(a));
}
// B-fragment from [n][k] storage: one n-tile (x2)
__device__ __forceinline__ void ldsm2h_n(unsigned& r0, unsigned& r1,
                                         const __half* base, int n0, int k0, int stride) {
    const int l4 = threadIdx.x & 15;
    uint32_t a = sptr(base + (n0 + (l4 & 7)) * stride + k0 + ((l4 >> 3) << 3));
    asm volatile("ldmatrix.sync.aligned.m8n8.x2.shared.b16 {%0,%1},[%2];"
                 : "=r"(r0), "=r"(r1) : "r"(a));
}
// B-fragments from [n][k] storage: TWO adjacent n-tiles (n0, n0+8) in one x4
__device__ __forceinline__ void ldsm4h_n(unsigned& r0, unsigned& r1, unsigned& r2, unsigned& r3,
                                         const __half* base, int n0, int k0, int stride) {
    const int lane = threadIdx.x & 31;
    uint32_t a = sptr(base + (n0 + (lane & 7) + ((lane >> 4) << 3)) * stride
                      + k0 + (((lane >> 3) & 1) << 3));
    asm volatile("ldmatrix.sync.aligned.m8n8.x4.shared.b16 {%0,%1,%2,%3},[%4];"
                 : "=r"(r0), "=r"(r1), "=r"(r2), "=r"(r3) : "r"(a));
}
// B-fragments from [k][n] storage: k-steps k0 and k0+16 of one n-tile (x4 trans)
__device__ __forceinline__ void ldsm4h_t(unsigned& r0, unsigned& r1, unsigned& r2, unsigned& r3,
                                         const __half* base, int k0, int n0, int stride) {
    const int lane = threadIdx.x & 31;
    uint32_t a = sptr(base + (k0 + lane) * stride + n0);
    asm volatile("ldmatrix.sync.aligned.m8n8.x4.trans.shared.b16 {%0,%1,%2,%3},[%4];"
                 : "=r"(r0), "=r"(r1), "=r"(r2), "=r"(r3) : "r"(a));
}

// ---------------- K1: nf = gather(X) @ w2^T + b2 ----------------------------
__global__ void __launch_bounds__(256) k_nf(const float* __restrict__ x,
                                            const float* __restrict__ w2,
                                            const float* __restrict__ b2) {
    __shared__ __half xh[64 * 72];
    __shared__ __half wh[64 * 72];
    const int tile = blockIdx.x, batch = blockIdx.y, tid = threadIdx.x;
    const int b = batch / LWIN, l = batch % LWIN;

    for (int e = tid; e < 1024; e += 256) {
        const int row = e >> 4, c4 = e & 15;
        const int r = tile * 64 + row, m = r >> 8, n = r & 255;
        float4 xv = *(const float4*)(x + ((size_t)(b * SEQ + l + m) * NNODE + n) * FDIM + c4 * 4);
        *(__half2*)(xh + row * 72 + c4 * 4)     = __floats2half2_rn(xv.x, xv.y);
        *(__half2*)(xh + row * 72 + c4 * 4 + 2) = __floats2half2_rn(xv.z, xv.w);
        float4 wv = *(const float4*)(w2 + row * 64 + c4 * 4);
        *(__half2*)(wh + row * 72 + c4 * 4)     = __floats2half2_rn(wv.x, wv.y);
        *(__half2*)(wh + row * 72 + c4 * 4 + 2) = __floats2half2_rn(wv.z, wv.w);
    }
    __syncthreads();

    const int w = tid >> 5, lane = tid & 31;
    const int band = w >> 1, colg = w & 1;
    const int lq = lane >> 2, lr = lane & 3;
    float acc[4][4];
#pragma unroll
    for (int t = 0; t < 4; t++) { acc[t][0] = acc[t][1] = acc[t][2] = acc[t][3] = 0.f; }
#pragma unroll
    for (int ks = 0; ks < 4; ks++) {
        const int k0 = ks * 16;
        unsigned a0, a1, a2, a3; ldsm4h(a0, a1, a2, a3, xh, band * 16, k0, 72);
#pragma unroll
        for (int tt = 0; tt < 2; tt++) {
            unsigned b0, b1, b2v, b3v;
            ldsm4h_n(b0, b1, b2v, b3v, wh, colg * 32 + tt * 16, k0, 72);
            mma_f16(acc[tt * 2],     a0, a1, a2, a3, b0, b1);
            mma_f16(acc[tt * 2 + 1], a0, a1, a2, a3, b2v, b3v);
        }
    }
    const size_t ob = ((size_t)batch * N1 + tile * 64 + band * 16 + lq) * 64;
#pragma unroll
    for (int t = 0; t < 4; t++) {
        const int c = colg * 32 + t * 8 + lr * 2;
        const float bb0 = __ldg(b2 + c), bb1 = __ldg(b2 + c + 1);
        *(__half2*)(g_nfh + ob + c) = __floats2half2_rn(acc[t][0] + bb0, acc[t][1] + bb1);
        *(__half2*)(g_nfh + ob + (size_t)8 * 64 + c) = __floats2half2_rn(acc[t][2] + bb0, acc[t][3] + bb1);
    }
}

// ---------------- BN stats (streaming, half sources) --------------------------
__global__ void k_stats_p1(int which) {
    const int batch = blockIdx.x, tid = threadIdx.x;
    const int c = tid & 63, rg = tid >> 6;
    const __half* p = ((which == 0) ? g_nfh : g_oph) + (size_t)batch * N1 * 64;
    float s = 0.f, q = 0.f;
    for (int r = rg * 128; r < rg * 128 + 128; r++) {
        float v = __half2float(p[(size_t)r * 64 + c]);
        s += v; q += v * v;
    }
    __shared__ float sm[256], qm[256];
    sm[tid] = s; qm[tid] = q;
    __syncthreads();
    if (tid < 64) {
        g_part[which][batch][tid]      = sm[tid] + sm[tid + 64] + sm[tid + 128] + sm[tid + 192];
        g_part[which][batch][tid + 64] = qm[tid] + qm[tid + 64] + qm[tid + 128] + qm[tid + 192];
    }
}
__global__ void k_stats_p2(const float* __restrict__ w, const float* __restrict__ bb, int which) {
    const int c = threadIdx.x;
    float s = 0.f, q = 0.f;
    for (int b2 = 0; b2 < BP; b2++) { s += g_part[which][b2][c]; q += g_part[which][b2][c + 64]; }
    const float mu  = s / (float)NTOT;
    const float var = q / (float)NTOT - mu * mu;
    const float a   = w[c] * rsqrtf(var + 1e-5f);
    g_coef[which][0][c] = a;
    g_coef[which][1][c] = bb[c] - mu * a;
}

// ---------------- K1b: theta fold, parallel (128 blocks x 64 thr) -----------
__global__ void k_prep(const float* __restrict__ th0w, const float* __restrict__ th1w) {
    const int n = blockIdx.x, k = threadIdx.x;
    const float* wr = (n < 64) ? (th0w + n * 64) : (th1w + (n - 64) * 64);
    const float wv = wr[k];
    g_Wh[n * 64 + k] = __float2half(wv * g_coef[0][0][k]);
    float c = wv * g_coef[0][1][k];
#pragma unroll
    for (int o = 16; o > 0; o >>= 1) c += __shfl_xor_sync(~0u, c, o);
    __shared__ float sc[2];
    if ((k & 31) == 0) sc[k >> 5] = c;
    __syncthreads();
    if (k == 0) g_cbuf[n] = sc[0] + sc[1];
}

// ---------------- K2: w1 = xb@th1^T only (z1 folded into k_adj) -------------
// smem bytes: nfh[64*72]h @0 | Wh1[64*72]h @9216 | cbuf[64]f @18432
__global__ void __launch_bounds__(256) k_pre() {
    extern __shared__ char sraw[];
    __half* nfh  = (__half*)sraw;
    __half* Wh1  = (__half*)(sraw + 9216);
    float*  cbuf = (float*)(sraw + 18432);
    const int tile = blockIdx.x, batch = blockIdx.y, tid = threadIdx.x;

    for (int e = tid; e < 512; e += 256) {
        const int row = e >> 3, c8 = e & 7;
        cp16(sptr(nfh + row * 72 + c8 * 8),
             g_nfh + ((size_t)batch * N1 + tile * 64 + row) * 64 + c8 * 8);
        cp16(sptr(Wh1 + row * 72 + c8 * 8), g_Wh + (64 + row) * 64 + c8 * 8);
    }
    if (tid < 16) cp16(sptr(cbuf + tid * 4), g_cbuf + 64 + tid * 4);
    CP_COMMIT; CP_WAIT0;
    __syncthreads();

    const int w = tid >> 5, lane = tid & 31;
    const int band = w >> 1, colg = w & 1;
    const int lq = lane >> 2, lr = lane & 3;
    float acc[4][4];
#pragma unroll
    for (int t = 0; t < 4; t++) { acc[t][0] = acc[t][1] = acc[t][2] = acc[t][3] = 0.f; }
#pragma unroll
    for (int ks = 0; ks < 4; ks++) {
        const int k0 = ks * 16;
        unsigned a0, a1, a2, a3; ldsm4h(a0, a1, a2, a3, nfh, band * 16, k0, 72);
#pragma unroll
        for (int tt = 0; tt < 2; tt++) {
            unsigned b0, b1, b2v, b3v;
            ldsm4h_n(b0, b1, b2v, b3v, Wh1, colg * 32 + tt * 16, k0, 72);
            mma_f16(acc[tt * 2],     a0, a1, a2, a3, b0, b1);
            mma_f16(acc[tt * 2 + 1], a0, a1, a2, a3, b2v, b3v);
        }
    }
    const size_t rbase = (size_t)batch * N1 + tile * 64 + band * 16 + lq;
#pragma unroll
    for (int t = 0; t < 4; t++) {
        const int n = colg * 32 + t * 8 + lr * 2;
        const float c0 = cbuf[n], c1 = cbuf[n + 1];
        *(__half2*)(g_w1h + rbase * 64 + n) = __floats2half2_rn(acc[t][0] + c0, acc[t][1] + c1);
        *(__half2*)(g_w1h + (rbase + 8) * 64 + n) = __floats2half2_rn(acc[t][2] + c0, acc[t][3] + c1);
    }
}

// ---------------- K3: adj (softmax) + z1 fold + t = z1 + adj@w1 -------------
// smem bytes: nf_s[512*72]h @0 | adj_s[32*520]h @73728 (Wh0 aliases its head)
//             reds[32*8]f @107008 | cb0[64]f @108032
__global__ void __launch_bounds__(512, 2) k_adj() {
    extern __shared__ char sraw[];
    __half* nf_s  = (__half*)sraw;            // later reused as w1 buffer
    __half* adj_s = (__half*)(sraw + 73728);
    __half* Wh0   = adj_s;                     // alias: consumed before softmax writes
    float*  reds  = (float*)(sraw + 107008);
    float*  cb0   = (float*)(sraw + 108032);
    const int tile = blockIdx.x, batch = blockIdx.y, tid = threadIdx.x;

    const __half* nfg = g_nfh + (size_t)batch * N1 * 64;
    for (int e = tid; e < 4096; e += 512)
        cp16(sptr(nf_s + (e >> 3) * 72 + (e & 7) * 8), nfg + e * 8);
    for (int e = tid; e < 512; e += 512)
        cp16(sptr(Wh0 + (e >> 3) * 72 + (e & 7) * 8), g_Wh + e * 8);
    if (tid < 16) cp16(sptr(cb0 + tid * 4), g_cbuf + tid * 4);
    CP_COMMIT; CP_WAIT0;
    __syncthreads();

    const int w = tid >> 5, lane = tid & 31;
    const int band = w >> 3, colg = w & 7;
    const int lq = lane >> 2, lr = lane & 3;
    const int rl0 = band * 16 + lq;
    const int rg0 = tile * 32 + rl0, rg1 = rg0 + 8;
    const int n0 = colg * 8;

    // ---- scores (32x512) + z1 fold (32x8 per warp, riding the A-frags) ----
    float acc[8][4];
#pragma unroll
    for (int t = 0; t < 8; t++) { acc[t][0] = acc[t][1] = acc[t][2] = acc[t][3] = 0.f; }
    float va[4] = {0.f, 0.f, 0.f, 0.f};
#pragma unroll
    for (int ks = 0; ks < 4; ks++) {
        const int k0 = ks * 16;
        unsigned a0, a1, a2, a3; ldsm4h(a0, a1, a2, a3, nf_s, tile * 32 + band * 16, k0, 72);
#pragma unroll
        for (int tt = 0; tt < 4; tt++) {
            unsigned b0, b1, b2v, b3v;
            ldsm4h_n(b0, b1, b2v, b3v, nf_s, colg * 64 + tt * 16, k0, 72);
            mma_f16(acc[tt * 2],     a0, a1, a2, a3, b0, b1);
            mma_f16(acc[tt * 2 + 1], a0, a1, a2, a3, b2v, b3v);
        }
        unsigned z0, z1; ldsm2h_n(z0, z1, Wh0, n0, k0, 72);
        mma_f16(va, a0, a1, a2, a3, z0, z1);
    }
    __syncthreads();   // all reads of nf_s / Wh0 (MMA operands) complete

    // prefetch w1 into nf_s while doing softmax
    const __half* w1g = g_w1h + (size_t)batch * N1 * 64;
    for (int e = tid; e < 4096; e += 512)
        cp16(sptr(nf_s + (e >> 3) * 72 + (e & 7) * 8), w1g + e * 8);
    CP_COMMIT;

    float s0 = 0.f, s1 = 0.f;
#pragma unroll
    for (int t = 0; t < 8; t++) {
#pragma unroll
        for (int j = 0; j < 2; j++) {
            const int col = colg * 64 + t * 8 + lr * 2 + j;
            float v = acc[t][j];
            if (col == rg0) v -= 1e8f;
            v = v > 0.f ? v : SLOPE * v;
            float e0 = __expf(v); acc[t][j] = e0; s0 += e0;
            float u = acc[t][2 + j];
            if (col == rg1) u -= 1e8f;
            u = u > 0.f ? u : SLOPE * u;
            float e1 = __expf(u); acc[t][2 + j] = e1; s1 += e1;
        }
    }
    s0 += __shfl_xor_sync(~0u, s0, 1); s0 += __shfl_xor_sync(~0u, s0, 2);
    s1 += __shfl_xor_sync(~0u, s1, 1); s1 += __shfl_xor_sync(~0u, s1, 2);
    if (lr == 0) { reds[rl0 * 8 + colg] = s0; reds[(rl0 + 8) * 8 + colg] = s1; }
    __syncthreads();
    float t0 = 0.f, t1 = 0.f;
#pragma unroll
    for (int c = 0; c < 8; c++) { t0 += reds[rl0 * 8 + c]; t1 += reds[(rl0 + 8) * 8 + c]; }
    const float inv0 = 1.f / t0, inv1 = 1.f / t1;
    const float msk = ((tile >= 8) != (colg >= 4)) ? 0.7f : 1.0f;

#pragma unroll
    for (int t = 0; t < 8; t++) {
#pragma unroll
        for (int j = 0; j < 2; j++) {
            const int col = colg * 64 + t * 8 + lr * 2 + j;
            float v = acc[t][j] * inv0;     if (col == rg0) v += 1.f;
            adj_s[rl0 * 520 + col] = __float2half(v * msk);
            float u = acc[t][2 + j] * inv1; if (col == rg1) u += 1.f;
            adj_s[(rl0 + 8) * 520 + col] = __float2half(u * msk);
        }
    }
    CP_WAIT0;
    __syncthreads();

    {
        const size_t gb = ((size_t)batch * N1 + tile * 32) * N1;
        for (int e = tid; e < 2048; e += 512) {
            const int r = e >> 6, c8 = e & 63;
            *(uint4*)(g_adjh + gb + (size_t)r * N1 + c8 * 8) =
                *(const uint4*)(adj_s + r * 520 + c8 * 8);
        }
    }

    // ---- va += adj @ w1 ; t = va + vb + c0 ----
    float vb[4] = {0.f, 0.f, 0.f, 0.f};
#pragma unroll 4
    for (int ks = 0; ks < 32; ks += 2) {
        const int k0 = ks * 16;
        unsigned a0, a1, a2, a3; ldsm4h(a0, a1, a2, a3, adj_s, band * 16, k0, 520);
        unsigned c0, c1, c2, c3; ldsm4h(c0, c1, c2, c3, adj_s, band * 16, k0 + 16, 520);
        unsigned b0, b1, b2v, b3v; ldsm4h_t(b0, b1, b2v, b3v, nf_s, k0, n0, 72);
        mma_f16(va, a0, a1, a2, a3, b0, b1);
        mma_f16(vb, c0, c1, c2, c3, b2v, b3v);
    }
    const size_t rb = (size_t)batch * N1 + tile * 32 + band * 16 + lq;
    const int cA = n0 + lr * 2;
    const float cz0 = cb0[cA], cz1 = cb0[cA + 1];
    *(__half2*)(g_th + rb * 64 + cA) =
        __floats2half2_rn(va[0] + vb[0] + cz0, va[1] + vb[1] + cz1);
    *(__half2*)(g_th + (rb + 8) * 64 + cA) =
        __floats2half2_rn(va[2] + vb[2] + cz0, va[3] + vb[3] + cz1);
}

// ---------------- K4: op = adj @ t + (th0b+th1b), 64-row tiles --------------
__global__ void __launch_bounds__(512, 2) k_out(const float* __restrict__ th0b,
                                                const float* __restrict__ th1b) {
    extern __shared__ char sraw[];
    __half* t_s = (__half*)sraw;
    __half* cbA = (__half*)(sraw + 73728);
    __half* cbB = (__half*)(sraw + 91136);
    const int tile = blockIdx.x, batch = blockIdx.y, tid = threadIdx.x;

    const __half* tg = g_th + (size_t)batch * N1 * 64;
    const __half* ag = g_adjh + ((size_t)batch * N1 + tile * 64) * N1;
    for (int e = tid; e < 4096; e += 512)
        cp16(sptr(t_s + (e >> 3) * 72 + (e & 7) * 8), tg + e * 8);
    for (int e = tid; e < 1024; e += 512) {
        const int r = e >> 4, c8 = e & 15;
        cp16(sptr(cbA + r * 136 + c8 * 8), ag + (size_t)r * N1 + c8 * 8);
    }
    CP_COMMIT;

    const int w = tid >> 5, lane = tid & 31;
    const int band = w >> 2, colg = w & 3;
    const int lq = lane >> 2, lr = lane & 3;
    float acc[2][4];
#pragma unroll
    for (int t = 0; t < 2; t++) { acc[t][0] = acc[t][1] = acc[t][2] = acc[t][3] = 0.f; }

    for (int ch = 0; ch < 4; ch++) {
        __half* cb = (ch & 1) ? cbB : cbA;
        if (ch < 3) {
            __half* nb = (ch & 1) ? cbA : cbB;
            for (int e = tid; e < 1024; e += 512) {
                const int r = e >> 4, c8 = e & 15;
                cp16(sptr(nb + r * 136 + c8 * 8), ag + (size_t)r * N1 + (ch + 1) * 128 + c8 * 8);
            }
            CP_COMMIT; CP_WAIT1;
        } else {
            CP_WAIT0;
        }
        __syncthreads();
#pragma unroll
        for (int ks = 0; ks < 8; ks += 2) {
            const int k0 = ks * 16;
            unsigned a0, a1, a2, a3; ldsm4h(a0, a1, a2, a3, cb, band * 16, k0, 136);
            unsigned c0, c1, c2, c3; ldsm4h(c0, c1, c2, c3, cb, band * 16, k0 + 16, 136);
#pragma unroll
            for (int nt = 0; nt < 2; nt++) {
                unsigned b0, b1, b2v, b3v;
                ldsm4h_t(b0, b1, b2v, b3v, t_s, ch * 128 + k0, colg * 16 + nt * 8, 72);
                mma_f16(acc[nt], a0, a1, a2, a3, b0, b1);
                mma_f16(acc[nt], c0, c1, c2, c3, b2v, b3v);
            }
        }
        __syncthreads();
    }
    const size_t rb = (size_t)batch * N1 + tile * 64 + band * 16 + lq;
#pragma unroll
    for (int nt = 0; nt < 2; nt++) {
        const int cA = colg * 16 + nt * 8 + lr * 2;
        const float bc0 = __ldg(th0b + cA) + __ldg(th1b + cA);
        const float bc1 = __ldg(th0b + cA + 1) + __ldg(th1b + cA + 1);
        *(__half2*)(g_oph + rb * 64 + cA) = __floats2half2_rn(acc[nt][0] + bc0, acc[nt][1] + bc1);
        *(__half2*)(g_oph + (rb + 8) * 64 + cA) = __floats2half2_rn(acc[nt][2] + bc0, acc[nt][3] + bc1);
    }
}

// ---------------- K5: BN1 affine + leaky + mean pool (half2 reads) -----------
__global__ void k_final(float* __restrict__ out) {
    const int idx = blockIdx.x * 256 + threadIdx.x;
    const int c2 = idx & 31;
    const int n = (idx >> 5) & 255;
    const int b = idx >> 13;
    const float a0 = g_coef[1][0][c2 * 2], a1 = g_coef[1][0][c2 * 2 + 1];
    const float d0 = g_coef[1][1][c2 * 2], d1 = g_coef[1][1][c2 * 2 + 1];
    float s0 = 0.f, s1 = 0.f;
#pragma unroll 2
    for (int l = 0; l < LWIN; l++)
#pragma unroll
        for (int m = 0; m < 2; m++) {
            __half2 h = *(const __half2*)(g_oph +
                (((size_t)(b * LWIN + l) * N1 + m * NNODE + n) << 6) + c2 * 2);
            float2 f = __half22float2(h);
            float v0 = a0 * f.x + d0; s0 += (v0 > 0.f) ? v0 : SLOPE * v0;
            float v1 = a1 * f.y + d1; s1 += (v1 > 0.f) ? v1 : SLOPE * v1;
        }
    *(float2*)(out + (((size_t)(b * NNODE + n)) << 6) + c2 * 2) =
        make_float2(s0 * (1.f / 32.f), s1 * (1.f / 32.f));
}

// ---------------- launch ------------------------------------------------------
extern "C" void kernel_launch(void* const* d_in, const int* in_sizes, int n_in,
                              void* d_out, int out_size) {
    const float* x    = (const float*)d_in[0];
    const float* w2   = (const float*)d_in[1];
    const float* b2   = (const float*)d_in[2];
    const float* bn0w = (const float*)d_in[3];
    const float* bn0b = (const float*)d_in[4];
    const float* th0w = (const float*)d_in[5];
    const float* th0b = (const float*)d_in[6];
    const float* th1w = (const float*)d_in[7];
    const float* th1b = (const float*)d_in[8];
    const float* bn1w = (const float*)d_in[9];
    const float* bn1b = (const float*)d_in[10];
    float* out = (float*)d_out;

    const int SMEM_PRE = 18688;
    const int SMEM_ADJ = 108288;
    const int SMEM_OUT = 108544;
    cudaFuncSetAttribute(k_pre, cudaFuncAttributeMaxDynamicSharedMemorySize, SMEM_PRE);
    cudaFuncSetAttribute(k_adj, cudaFuncAttributeMaxDynamicSharedMemorySize, SMEM_ADJ);
    cudaFuncSetAttribute(k_out, cudaFuncAttributeMaxDynamicSharedMemorySize, SMEM_OUT);

    k_nf<<<dim3(8, BP), 256>>>(x, w2, b2);
    k_stats_p1<<<BP, 256>>>(0);
    k_stats_p2<<<1, 64>>>(bn0w, bn0b, 0);
    k_prep<<<128, 64>>>(th0w, th1w);
    k_pre<<<dim3(8, BP), 256, SMEM_PRE>>>();
    k_adj<<<dim3(16, BP), 512, SMEM_ADJ>>>();
    k_out<<<dim3(8, BP), 512, SMEM_OUT>>>(th0b, th1b);
    k_stats_p1<<<BP, 256>>>(1);
    k_stats_p2<<<1, 64>>>(bn1w, bn1b, 1);
    k_final<<<512, 256>>>(out);
}

// round 10
// speedup vs baseline: 1.1981x; 1.0716x over previous
#include <cuda_runtime.h>
#include <cuda_fp16.h>
#include <math.h>
#include <stdint.h>

#define BATCH   16
#define SEQ     17
#define NNODE   256
#define FDIM    64
#define LWIN    16
#define BP      256         // BATCH*LWIN
#define N1      512
#define OUTD    64
#define NTOT    (BP*N1)
#define SLOPE   0.01f

// ---------------- scratch ----------------------------------------------------
__device__ __half g_nfh [(size_t)BP*N1*FDIM];
__device__ __half g_adjh[(size_t)BP*N1*N1];     // 134 MB
__device__ __half g_th  [(size_t)BP*N1*FDIM];
__device__ __half g_oph [(size_t)BP*N1*OUTD];
__device__ float  g_part[2][BP][128];
__device__ float  g_coef[2][2][64];             // [1] used by k_final
__device__ __half g_Wh  [128*64];               // rows 0-63: th0*a ; 64-127: th1*a
__device__ float  g_cbuf[128];                  // [0..64): th0@d ; [64..128): th1@d

// ---------------- helpers ----------------------------------------------------
__device__ __forceinline__ uint32_t sptr(const void* p) {
    return (uint32_t)__cvta_generic_to_shared(p);
}
__device__ __forceinline__ void cp16(uint32_t d, const void* s) {
    asm volatile("cp.async.cg.shared.global [%0],[%1],16;" :: "r"(d), "l"(s));
}
#define CP_COMMIT asm volatile("cp.async.commit_group;")
#define CP_WAIT0  asm volatile("cp.async.wait_group 0;")
#define CP_WAIT1  asm volatile("cp.async.wait_group 1;")

__device__ __forceinline__ void mma_f16(float c[4], unsigned a0, unsigned a1,
                                        unsigned a2, unsigned a3,
                                        unsigned b0, unsigned b1) {
    asm volatile(
        "mma.sync.aligned.m16n8k16.row.col.f32.f16.f16.f32 "
        "{%0,%1,%2,%3},{%4,%5,%6,%7},{%8,%9},{%0,%1,%2,%3};"
        : "+f"(c[0]), "+f"(c[1]), "+f"(c[2]), "+f"(c[3])
        : "r"(a0), "r"(a1), "r"(a2), "r"(a3), "r"(b0), "r"(b1));
}
// A-fragment (16x16), row-major [m][k]
__device__ __forceinline__ void ldsm4h(unsigned& r0, unsigned& r1, unsigned& r2, unsigned& r3,
                                       const __half* base, int row0, int k0, int stride) {
    const int lane = threadIdx.x & 31;
    uint32_t a = sptr(base + (row0 + (lane & 15)) * stride + k0 + ((lane >> 4) << 3));
    asm volatile("ldmatrix.sync.aligned.m8n8.x4.shared.b16 {%0,%1,%2,%3},[%4];"
                 : "=r"(r0), "=r"(r1), "=r"(r2), "=r"(r3) : "r"(a));
}
// B-fragment from [n][k] storage: one n-tile (x2)
__device__ __forceinline__ void ldsm2h_n(unsigned& r0, unsigned& r1,
                                         const __half* base, int n0, int k0, int stride) {
    const int l4 = threadIdx.x & 15;
    uint32_t a = sptr(base + (n0 + (l4 & 7)) * stride + k0 + ((l4 >> 3) << 3));
    asm volatile("ldmatrix.sync.aligned.m8n8.x2.shared.b16 {%0,%1},[%2];"
                 : "=r"(r0), "=r"(r1) : "r"(a));
}
// B-fragments from [n][k] storage: TWO adjacent n-tiles (n0, n0+8) in one x4
__device__ __forceinline__ void ldsm4h_n(unsigned& r0, unsigned& r1, unsigned& r2, unsigned& r3,
                                         const __half* base, int n0, int k0, int stride) {
    const int lane = threadIdx.x & 31;
    uint32_t a = sptr(base + (n0 + (lane & 7) + ((lane >> 4) << 3)) * stride
                      + k0 + (((lane >> 3) & 1) << 3));
    asm volatile("ldmatrix.sync.aligned.m8n8.x4.shared.b16 {%0,%1,%2,%3},[%4];"
                 : "=r"(r0), "=r"(r1), "=r"(r2), "=r"(r3) : "r"(a));
}
// B-fragments from [k][n] storage: k-steps k0 and k0+16 of one n-tile (x4 trans)
__device__ __forceinline__ void ldsm4h_t(unsigned& r0, unsigned& r1, unsigned& r2, unsigned& r3,
                                         const __half* base, int k0, int n0, int stride) {
    const int lane = threadIdx.x & 31;
    uint32_t a = sptr(base + (k0 + lane) * stride + n0);
    asm volatile("ldmatrix.sync.aligned.m8n8.x4.trans.shared.b16 {%0,%1,%2,%3},[%4];"
                 : "=r"(r0), "=r"(r1), "=r"(r2), "=r"(r3) : "r"(a));
}

// ---------------- K1: nf = gather(X) @ w2^T + b2 ----------------------------
__global__ void __launch_bounds__(256) k_nf(const float* __restrict__ x,
                                            const float* __restrict__ w2,
                                            const float* __restrict__ b2) {
    __shared__ __half xh[64 * 72];
    __shared__ __half wh[64 * 72];
    const int tile = blockIdx.x, batch = blockIdx.y, tid = threadIdx.x;
    const int b = batch / LWIN, l = batch % LWIN;

    for (int e = tid; e < 1024; e += 256) {
        const int row = e >> 4, c4 = e & 15;
        const int r = tile * 64 + row, m = r >> 8, n = r & 255;
        float4 xv = *(const float4*)(x + ((size_t)(b * SEQ + l + m) * NNODE + n) * FDIM + c4 * 4);
        *(__half2*)(xh + row * 72 + c4 * 4)     = __floats2half2_rn(xv.x, xv.y);
        *(__half2*)(xh + row * 72 + c4 * 4 + 2) = __floats2half2_rn(xv.z, xv.w);
        float4 wv = *(const float4*)(w2 + row * 64 + c4 * 4);
        *(__half2*)(wh + row * 72 + c4 * 4)     = __floats2half2_rn(wv.x, wv.y);
        *(__half2*)(wh + row * 72 + c4 * 4 + 2) = __floats2half2_rn(wv.z, wv.w);
    }
    __syncthreads();

    const int w = tid >> 5, lane = tid & 31;
    const int band = w >> 1, colg = w & 1;
    const int lq = lane >> 2, lr = lane & 3;
    float acc[4][4];
#pragma unroll
    for (int t = 0; t < 4; t++) { acc[t][0] = acc[t][1] = acc[t][2] = acc[t][3] = 0.f; }
#pragma unroll
    for (int ks = 0; ks < 4; ks++) {
        const int k0 = ks * 16;
        unsigned a0, a1, a2, a3; ldsm4h(a0, a1, a2, a3, xh, band * 16, k0, 72);
#pragma unroll
        for (int tt = 0; tt < 2; tt++) {
            unsigned b0, b1, b2v, b3v;
            ldsm4h_n(b0, b1, b2v, b3v, wh, colg * 32 + tt * 16, k0, 72);
            mma_f16(acc[tt * 2],     a0, a1, a2, a3, b0, b1);
            mma_f16(acc[tt * 2 + 1], a0, a1, a2, a3, b2v, b3v);
        }
    }
    const size_t ob = ((size_t)batch * N1 + tile * 64 + band * 16 + lq) * 64;
#pragma unroll
    for (int t = 0; t < 4; t++) {
        const int c = colg * 32 + t * 8 + lr * 2;
        const float bb0 = __ldg(b2 + c), bb1 = __ldg(b2 + c + 1);
        *(__half2*)(g_nfh + ob + c) = __floats2half2_rn(acc[t][0] + bb0, acc[t][1] + bb1);
        *(__half2*)(g_nfh + ob + (size_t)8 * 64 + c) = __floats2half2_rn(acc[t][2] + bb0, acc[t][3] + bb1);
    }
}

// ---------------- BN stats (streaming, half sources) --------------------------
__global__ void k_stats_p1(int which) {
    const int batch = blockIdx.x, tid = threadIdx.x;
    const int c = tid & 63, rg = tid >> 6;
    const __half* p = ((which == 0) ? g_nfh : g_oph) + (size_t)batch * N1 * 64;
    float s = 0.f, q = 0.f;
    for (int r = rg * 128; r < rg * 128 + 128; r++) {
        float v = __half2float(p[(size_t)r * 64 + c]);
        s += v; q += v * v;
    }
    __shared__ float sm[256], qm[256];
    sm[tid] = s; qm[tid] = q;
    __syncthreads();
    if (tid < 64) {
        g_part[which][batch][tid]      = sm[tid] + sm[tid + 64] + sm[tid + 128] + sm[tid + 192];
        g_part[which][batch][tid + 64] = qm[tid] + qm[tid + 64] + qm[tid + 128] + qm[tid + 192];
    }
}
__global__ void k_stats_p2(const float* __restrict__ w, const float* __restrict__ bb, int which) {
    const int c = threadIdx.x;
    float s = 0.f, q = 0.f;
    for (int b2 = 0; b2 < BP; b2++) { s += g_part[which][b2][c]; q += g_part[which][b2][c + 64]; }
    const float mu  = s / (float)NTOT;
    const float var = q / (float)NTOT - mu * mu;
    const float a   = w[c] * rsqrtf(var + 1e-5f);
    g_coef[which][0][c] = a;
    g_coef[which][1][c] = bb[c] - mu * a;
}

// ---------------- K1b: BN0 coefs + theta fold, fused (1 CTA, 128 thr) --------
__global__ void k_p2prep(const float* __restrict__ bn0w, const float* __restrict__ bn0b,
                         const float* __restrict__ th0w, const float* __restrict__ th1w) {
    __shared__ float ca[64], cd[64];
    const int tid = threadIdx.x;    // 128
    if (tid < 64) {
        float s = 0.f, q = 0.f;
        for (int b2 = 0; b2 < BP; b2++) { s += g_part[0][b2][tid]; q += g_part[0][b2][tid + 64]; }
        const float mu  = s / (float)NTOT;
        const float var = q / (float)NTOT - mu * mu;
        const float a   = bn0w[tid] * rsqrtf(var + 1e-5f);
        ca[tid] = a; cd[tid] = bn0b[tid] - mu * a;
    }
    __syncthreads();
    const int n = tid;
    const float* wr = (n < 64) ? (th0w + n * 64) : (th1w + (n - 64) * 64);
    float c = 0.f;
#pragma unroll 8
    for (int k = 0; k < 64; k++) {
        const float wv = wr[k];
        g_Wh[n * 64 + k] = __float2half(wv * ca[k]);
        c += wv * cd[k];
    }
    g_cbuf[n] = c;
}

// ---------------- K3: adj (softmax) + z1 fold + y=adj@nf + t = y@th1'^T ------
// smem bytes: nf_s[512*72]h @0 (reused: y_s head / Wh1 at +4608)
//             adj_s[32*520]h @73728 (Wh0 aliases head)
//             reds[32*8]f @107008 | cbuf_s[128]f @108032 | rowsum_s[32]f @108544
__global__ void __launch_bounds__(512, 2) k_adj() {
    extern __shared__ char sraw[];
    __half* nf_s  = (__half*)sraw;
    __half* adj_s = (__half*)(sraw + 73728);
    __half* Wh0   = adj_s;                     // consumed before softmax writes
    float*  reds  = (float*)(sraw + 107008);
    float*  cbuf_s= (float*)(sraw + 108032);
    float*  rowsum_s = (float*)(sraw + 108544);
    const int tile = blockIdx.x, batch = blockIdx.y, tid = threadIdx.x;

    const __half* nfg = g_nfh + (size_t)batch * N1 * 64;
    for (int e = tid; e < 4096; e += 512)
        cp16(sptr(nf_s + (e >> 3) * 72 + (e & 7) * 8), nfg + e * 8);
    for (int e = tid; e < 512; e += 512)
        cp16(sptr(Wh0 + (e >> 3) * 72 + (e & 7) * 8), g_Wh + e * 8);
    if (tid < 32) cp16(sptr(cbuf_s + tid * 4), g_cbuf + tid * 4);
    CP_COMMIT; CP_WAIT0;
    __syncthreads();

    const int w = tid >> 5, lane = tid & 31;
    const int band = w >> 3, colg = w & 7;
    const int lq = lane >> 2, lr = lane & 3;
    const int rl0 = band * 16 + lq;
    const int rg0 = tile * 32 + rl0, rg1 = rg0 + 8;
    const int n0 = colg * 8;

    // ---- scores (32x512) + z1 fold (va = nf@th0' for this tile's rows) ----
    float acc[8][4];
#pragma unroll
    for (int t = 0; t < 8; t++) { acc[t][0] = acc[t][1] = acc[t][2] = acc[t][3] = 0.f; }
    float va[4] = {0.f, 0.f, 0.f, 0.f};
#pragma unroll
    for (int ks = 0; ks < 4; ks++) {
        const int k0 = ks * 16;
        unsigned a0, a1, a2, a3; ldsm4h(a0, a1, a2, a3, nf_s, tile * 32 + band * 16, k0, 72);
#pragma unroll
        for (int tt = 0; tt < 4; tt++) {
            unsigned b0, b1, b2v, b3v;
            ldsm4h_n(b0, b1, b2v, b3v, nf_s, colg * 64 + tt * 16, k0, 72);
            mma_f16(acc[tt * 2],     a0, a1, a2, a3, b0, b1);
            mma_f16(acc[tt * 2 + 1], a0, a1, a2, a3, b2v, b3v);
        }
        unsigned z0, z1; ldsm2h_n(z0, z1, Wh0, n0, k0, 72);
        mma_f16(va, a0, a1, a2, a3, z0, z1);
    }
    __syncthreads();   // scores/zfold done reading nf_s & Wh0

    // ---- leaky + exp + partial sums ----
    float s0 = 0.f, s1 = 0.f;
#pragma unroll
    for (int t = 0; t < 8; t++) {
#pragma unroll
        for (int j = 0; j < 2; j++) {
            const int col = colg * 64 + t * 8 + lr * 2 + j;
            float v = acc[t][j];
            if (col == rg0) v -= 1e8f;
            v = v > 0.f ? v : SLOPE * v;
            float e0 = __expf(v); acc[t][j] = e0; s0 += e0;
            float u = acc[t][2 + j];
            if (col == rg1) u -= 1e8f;
            u = u > 0.f ? u : SLOPE * u;
            float e1 = __expf(u); acc[t][2 + j] = e1; s1 += e1;
        }
    }
    s0 += __shfl_xor_sync(~0u, s0, 1); s0 += __shfl_xor_sync(~0u, s0, 2);
    s1 += __shfl_xor_sync(~0u, s1, 1); s1 += __shfl_xor_sync(~0u, s1, 2);
    if (lr == 0) { reds[rl0 * 8 + colg] = s0; reds[(rl0 + 8) * 8 + colg] = s1; }
    __syncthreads();
    float lo0 = 0.f, hi0 = 0.f, lo1 = 0.f, hi1 = 0.f;
#pragma unroll
    for (int c = 0; c < 4; c++) {
        lo0 += reds[rl0 * 8 + c];       hi0 += reds[rl0 * 8 + 4 + c];
        lo1 += reds[(rl0 + 8) * 8 + c]; hi1 += reds[(rl0 + 8) * 8 + 4 + c];
    }
    const float inv0 = 1.f / (lo0 + hi0), inv1 = 1.f / (lo1 + hi1);
    const bool rlo = (tile < 8);
    if (colg == 0 && lr == 0) {
        rowsum_s[rl0]     = (rlo ? lo0 + 0.7f * hi0 : 0.7f * lo0 + hi0) * inv0 + 1.f;
        rowsum_s[rl0 + 8] = (rlo ? lo1 + 0.7f * hi1 : 0.7f * lo1 + hi1) * inv1 + 1.f;
    }
    const float msk = (rlo != (colg < 4)) ? 0.7f : 1.0f;

    // ---- normalize + eye + mask -> adj_s ----
#pragma unroll
    for (int t = 0; t < 8; t++) {
#pragma unroll
        for (int j = 0; j < 2; j++) {
            const int col = colg * 64 + t * 8 + lr * 2 + j;
            float v = acc[t][j] * inv0;     if (col == rg0) v += 1.f;
            adj_s[rl0 * 520 + col] = __float2half(v * msk);
            float u = acc[t][2 + j] * inv1; if (col == rg1) u += 1.f;
            adj_s[(rl0 + 8) * 520 + col] = __float2half(u * msk);
        }
    }
    __syncthreads();

    // ---- adj tile -> global ----
    {
        const size_t gb = ((size_t)batch * N1 + tile * 32) * N1;
        for (int e = tid; e < 2048; e += 512) {
            const int r = e >> 6, c8 = e & 63;
            *(uint4*)(g_adjh + gb + (size_t)r * N1 + c8 * 8) =
                *(const uint4*)(adj_s + r * 520 + c8 * 8);
        }
    }

    // ---- y = adj @ nf (nf still resident) ----
    float vy0[4] = {0.f, 0.f, 0.f, 0.f}, vy1[4] = {0.f, 0.f, 0.f, 0.f};
#pragma unroll 4
    for (int ks = 0; ks < 32; ks += 2) {
        const int k0 = ks * 16;
        unsigned a0, a1, a2, a3; ldsm4h(a0, a1, a2, a3, adj_s, band * 16, k0, 520);
        unsigned c0, c1, c2, c3; ldsm4h(c0, c1, c2, c3, adj_s, band * 16, k0 + 16, 520);
        unsigned b0, b1, b2v, b3v; ldsm4h_t(b0, b1, b2v, b3v, nf_s, k0, n0, 72);
        mma_f16(vy0, a0, a1, a2, a3, b0, b1);
        mma_f16(vy1, c0, c1, c2, c3, b2v, b3v);
    }
    __syncthreads();   // all reads of nf_s complete -> safe to overwrite

    // ---- stage y into nf_s head; fetch th1' into nf_s+4608B ----
    __half* y_s  = nf_s;
    __half* Wh1s = nf_s + 2304;
    {
        const int cA = n0 + lr * 2;
        *(__half2*)(y_s + rl0 * 72 + cA) =
            __floats2half2_rn(vy0[0] + vy1[0], vy0[1] + vy1[1]);
        *(__half2*)(y_s + (rl0 + 8) * 72 + cA) =
            __floats2half2_rn(vy0[2] + vy1[2], vy0[3] + vy1[3]);
    }
    for (int e = tid; e < 512; e += 512)
        cp16(sptr(Wh1s + (e >> 3) * 72 + (e & 7) * 8), g_Wh + 64 * 64 + e * 8);
    CP_COMMIT; CP_WAIT0;
    __syncthreads();

    // ---- t = va + y@th1'^T + rowsum*c1 + c0 ----
    float at[4] = {0.f, 0.f, 0.f, 0.f};
#pragma unroll
    for (int ks = 0; ks < 4; ks++) {
        const int k0 = ks * 16;
        unsigned a0, a1, a2, a3; ldsm4h(a0, a1, a2, a3, y_s, band * 16, k0, 72);
        unsigned b0, b1; ldsm2h_n(b0, b1, Wh1s, n0, k0, 72);
        mma_f16(at, a0, a1, a2, a3, b0, b1);
    }
    const size_t rb = (size_t)batch * N1 + tile * 32 + rl0;
    const int cA = n0 + lr * 2;
    const float c0a = cbuf_s[cA], c0b = cbuf_s[cA + 1];
    const float c1a = cbuf_s[64 + cA], c1b = cbuf_s[64 + cA + 1];
    const float rs0 = rowsum_s[rl0], rs1 = rowsum_s[rl0 + 8];
    *(__half2*)(g_th + rb * 64 + cA) =
        __floats2half2_rn(va[0] + at[0] + rs0 * c1a + c0a,
                          va[1] + at[1] + rs0 * c1b + c0b);
    *(__half2*)(g_th + (rb + 8) * 64 + cA) =
        __floats2half2_rn(va[2] + at[2] + rs1 * c1a + c0a,
                          va[3] + at[3] + rs1 * c1b + c0b);
}

// ---------------- K4: op = adj @ t + (th0b+th1b), 128-row tiles --------------
// smem bytes: t_s[512*72]h @0 | cbA[128*72]h @73728 | cbB @92160
__global__ void __launch_bounds__(512, 2) k_out(const float* __restrict__ th0b,
                                                const float* __restrict__ th1b) {
    extern __shared__ char sraw[];
    __half* t_s = (__half*)sraw;
    __half* cbA = (__half*)(sraw + 73728);
    __half* cbB = (__half*)(sraw + 92160);
    const int tile = blockIdx.x, batch = blockIdx.y, tid = threadIdx.x;

    const __half* tg = g_th + (size_t)batch * N1 * 64;
    const __half* ag = g_adjh + ((size_t)batch * N1 + tile * 128) * N1;
    for (int e = tid; e < 4096; e += 512)
        cp16(sptr(t_s + (e >> 3) * 72 + (e & 7) * 8), tg + e * 8);
    for (int e = tid; e < 1024; e += 512) {
        const int r = e >> 3, c8 = e & 7;
        cp16(sptr(cbA + r * 72 + c8 * 8), ag + (size_t)r * N1 + c8 * 8);
    }
    CP_COMMIT;

    const int w = tid >> 5, lane = tid & 31;
    const int band = w >> 1, colg = w & 1;        // 8 row-bands x 2 col-groups
    const int lq = lane >> 2, lr = lane & 3;
    float acc[4][4];
#pragma unroll
    for (int t = 0; t < 4; t++) { acc[t][0] = acc[t][1] = acc[t][2] = acc[t][3] = 0.f; }

    for (int ch = 0; ch < 8; ch++) {
        __half* cb = (ch & 1) ? cbB : cbA;
        if (ch < 7) {
            __half* nb = (ch & 1) ? cbA : cbB;
            for (int e = tid; e < 1024; e += 512) {
                const int r = e >> 3, c8 = e & 7;
                cp16(sptr(nb + r * 72 + c8 * 8), ag + (size_t)r * N1 + (ch + 1) * 64 + c8 * 8);
            }
            CP_COMMIT; CP_WAIT1;
        } else {
            CP_WAIT0;
        }
        __syncthreads();
#pragma unroll
        for (int kp = 0; kp < 64; kp += 32) {
            unsigned a0, a1, a2, a3; ldsm4h(a0, a1, a2, a3, cb, band * 16, kp, 72);
            unsigned c0, c1, c2, c3; ldsm4h(c0, c1, c2, c3, cb, band * 16, kp + 16, 72);
#pragma unroll
            for (int nt = 0; nt < 4; nt++) {
                unsigned b0, b1, b2v, b3v;
                ldsm4h_t(b0, b1, b2v, b3v, t_s, ch * 64 + kp, colg * 32 + nt * 8, 72);
                mma_f16(acc[nt], a0, a1, a2, a3, b0, b1);
                mma_f16(acc[nt], c0, c1, c2, c3, b2v, b3v);
            }
        }
        __syncthreads();
    }
    const size_t rb = (size_t)batch * N1 + tile * 128 + band * 16 + lq;
#pragma unroll
    for (int nt = 0; nt < 4; nt++) {
        const int cA = colg * 32 + nt * 8 + lr * 2;
        const float bc0 = __ldg(th0b + cA) + __ldg(th1b + cA);
        const float bc1 = __ldg(th0b + cA + 1) + __ldg(th1b + cA + 1);
        *(__half2*)(g_oph + rb * 64 + cA) = __floats2half2_rn(acc[nt][0] + bc0, acc[nt][1] + bc1);
        *(__half2*)(g_oph + (rb + 8) * 64 + cA) = __floats2half2_rn(acc[nt][2] + bc0, acc[nt][3] + bc1);
    }
}

// ---------------- K5: BN1 affine + leaky + mean pool (half2 reads) -----------
__global__ void k_final(float* __restrict__ out) {
    const int idx = blockIdx.x * 256 + threadIdx.x;
    const int c2 = idx & 31;
    const int n = (idx >> 5) & 255;
    const int b = idx >> 13;
    const float a0 = g_coef[1][0][c2 * 2], a1 = g_coef[1][0][c2 * 2 + 1];
    const float d0 = g_coef[1][1][c2 * 2], d1 = g_coef[1][1][c2 * 2 + 1];
    float s0 = 0.f, s1 = 0.f;
#pragma unroll 2
    for (int l = 0; l < LWIN; l++)
#pragma unroll
        for (int m = 0; m < 2; m++) {
            __half2 h = *(const __half2*)(g_oph +
                (((size_t)(b * LWIN + l) * N1 + m * NNODE + n) << 6) + c2 * 2);
            float2 f = __half22float2(h);
            float v0 = a0 * f.x + d0; s0 += (v0 > 0.f) ? v0 : SLOPE * v0;
            float v1 = a1 * f.y + d1; s1 += (v1 > 0.f) ? v1 : SLOPE * v1;
        }
    *(float2*)(out + (((size_t)(b * NNODE + n)) << 6) + c2 * 2) =
        make_float2(s0 * (1.f / 32.f), s1 * (1.f / 32.f));
}

// ---------------- launch ------------------------------------------------------
extern "C" void kernel_launch(void* const* d_in, const int* in_sizes, int n_in,
                              void* d_out, int out_size) {
    const float* x    = (const float*)d_in[0];
    const float* w2   = (const float*)d_in[1];
    const float* b2   = (const float*)d_in[2];
    const float* bn0w = (const float*)d_in[3];
    const float* bn0b = (const float*)d_in[4];
    const float* th0w = (const float*)d_in[5];
    const float* th0b = (const float*)d_in[6];
    const float* th1w = (const float*)d_in[7];
    const float* th1b = (const float*)d_in[8];
    const float* bn1w = (const float*)d_in[9];
    const float* bn1b = (const float*)d_in[10];
    float* out = (float*)d_out;

    const int SMEM_ADJ = 108672;
    const int SMEM_OUT = 110592;
    cudaFuncSetAttribute(k_adj, cudaFuncAttributeMaxDynamicSharedMemorySize, SMEM_ADJ);
    cudaFuncSetAttribute(k_out, cudaFuncAttributeMaxDynamicSharedMemorySize, SMEM_OUT);

    k_nf<<<dim3(8, BP), 256>>>(x, w2, b2);
    k_stats_p1<<<BP, 256>>>(0);
    k_p2prep<<<1, 128>>>(bn0w, bn0b, th0w, th1w);
    k_adj<<<dim3(16, BP), 512, SMEM_ADJ>>>();
    k_out<<<dim3(4, BP), 512, SMEM_OUT>>>(th0b, th1b);
    k_stats_p1<<<BP, 256>>>(1);
    k_stats_p2<<<1, 64>>>(bn1w, bn1b, 1);
    k_final<<<512, 256>>>(out);
}

// round 11
// speedup vs baseline: 1.2836x; 1.0713x over previous
#include <cuda_runtime.h>
#include <cuda_fp16.h>
#include <math.h>
#include <stdint.h>

#define BATCH   16
#define SEQ     17
#define NNODE   256
#define FDIM    64
#define LWIN    16
#define BP      256         // BATCH*LWIN
#define N1      512
#define OUTD    64
#define NTOT    (BP*N1)
#define SLOPE   0.01f

// ---------------- scratch ----------------------------------------------------
__device__ __half g_nfh [(size_t)BP*N1*FDIM];
__device__ __half g_adjh[(size_t)BP*N1*N1];     // 134 MB
__device__ __half g_th  [(size_t)BP*N1*FDIM];
__device__ __half g_oph [(size_t)BP*N1*OUTD];
__device__ float  g_part[2][BP][128];
__device__ float  g_coef[2][2][64];             // [1] used by k_final
__device__ __half g_Wh  [128*64];               // rows 0-63: th0*a ; 64-127: th1*a
__device__ float  g_cbuf[128];                  // [0..64): th0@d ; [64..128): th1@d

// ---------------- helpers ----------------------------------------------------
__device__ __forceinline__ uint32_t sptr(const void* p) {
    return (uint32_t)__cvta_generic_to_shared(p);
}
__device__ __forceinline__ void cp16(uint32_t d, const void* s) {
    asm volatile("cp.async.cg.shared.global [%0],[%1],16;" :: "r"(d), "l"(s));
}
#define CP_COMMIT asm volatile("cp.async.commit_group;")
#define CP_WAIT0  asm volatile("cp.async.wait_group 0;")
#define CP_WAIT1  asm volatile("cp.async.wait_group 1;")

__device__ __forceinline__ void mma_f16(float c[4], unsigned a0, unsigned a1,
                                        unsigned a2, unsigned a3,
                                        unsigned b0, unsigned b1) {
    asm volatile(
        "mma.sync.aligned.m16n8k16.row.col.f32.f16.f16.f32 "
        "{%0,%1,%2,%3},{%4,%5,%6,%7},{%8,%9},{%0,%1,%2,%3};"
        : "+f"(c[0]), "+f"(c[1]), "+f"(c[2]), "+f"(c[3])
        : "r"(a0), "r"(a1), "r"(a2), "r"(a3), "r"(b0), "r"(b1));
}
// A-fragment (16x16), row-major [m][k]
__device__ __forceinline__ void ldsm4h(unsigned& r0, unsigned& r1, unsigned& r2, unsigned& r3,
                                       const __half* base, int row0, int k0, int stride) {
    const int lane = threadIdx.x & 31;
    uint32_t a = sptr(base + (row0 + (lane & 15)) * stride + k0 + ((lane >> 4) << 3));
    asm volatile("ldmatrix.sync.aligned.m8n8.x4.shared.b16 {%0,%1,%2,%3},[%4];"
                 : "=r"(r0), "=r"(r1), "=r"(r2), "=r"(r3) : "r"(a));
}
// B-fragment from [n][k] storage: one n-tile (x2)
__device__ __forceinline__ void ldsm2h_n(unsigned& r0, unsigned& r1,
                                         const __half* base, int n0, int k0, int stride) {
    const int l4 = threadIdx.x & 15;
    uint32_t a = sptr(base + (n0 + (l4 & 7)) * stride + k0 + ((l4 >> 3) << 3));
    asm volatile("ldmatrix.sync.aligned.m8n8.x2.shared.b16 {%0,%1},[%2];"
                 : "=r"(r0), "=r"(r1) : "r"(a));
}
// B-fragments from [n][k] storage: TWO adjacent n-tiles (n0, n0+8) in one x4
__device__ __forceinline__ void ldsm4h_n(unsigned& r0, unsigned& r1, unsigned& r2, unsigned& r3,
                                         const __half* base, int n0, int k0, int stride) {
    const int lane = threadIdx.x & 31;
    uint32_t a = sptr(base + (n0 + (lane & 7) + ((lane >> 4) << 3)) * stride
                      + k0 + (((lane >> 3) & 1) << 3));
    asm volatile("ldmatrix.sync.aligned.m8n8.x4.shared.b16 {%0,%1,%2,%3},[%4];"
                 : "=r"(r0), "=r"(r1), "=r"(r2), "=r"(r3) : "r"(a));
}
// B-fragments from [k][n] storage: k-steps k0 and k0+16 of one n-tile (x4 trans)
__device__ __forceinline__ void ldsm4h_t(unsigned& r0, unsigned& r1, unsigned& r2, unsigned& r3,
                                         const __half* base, int k0, int n0, int stride) {
    const int lane = threadIdx.x & 31;
    uint32_t a = sptr(base + (k0 + lane) * stride + n0);
    asm volatile("ldmatrix.sync.aligned.m8n8.x4.trans.shared.b16 {%0,%1,%2,%3},[%4];"
                 : "=r"(r0), "=r"(r1), "=r"(r2), "=r"(r3) : "r"(a));
}
// Store a 16x16 accumulator tile (as half) via stmatrix x4. Same addr map as ldsm4h.
__device__ __forceinline__ void stsm4h(__half* base, int row0, int n0, int stride,
                                       unsigned p0, unsigned p1, unsigned p2, unsigned p3) {
    const int lane = threadIdx.x & 31;
    uint32_t a = sptr(base + (row0 + (lane & 15)) * stride + n0 + ((lane >> 4) << 3));
    asm volatile("stmatrix.sync.aligned.m8n8.x4.shared.b16 [%0], {%1,%2,%3,%4};"
                 :: "r"(a), "r"(p0), "r"(p1), "r"(p2), "r"(p3) : "memory");
}
__device__ __forceinline__ unsigned h2u(float a, float b) {
    __half2 h = __floats2half2_rn(a, b);
    return *reinterpret_cast<unsigned*>(&h);
}

// ---------------- K1: nf = gather(X) @ w2^T + b2 ----------------------------
__global__ void __launch_bounds__(256) k_nf(const float* __restrict__ x,
                                            const float* __restrict__ w2,
                                            const float* __restrict__ b2) {
    __shared__ __half xh[64 * 72];
    __shared__ __half wh[64 * 72];
    const int tile = blockIdx.x, batch = blockIdx.y, tid = threadIdx.x;
    const int b = batch / LWIN, l = batch % LWIN;

    for (int e = tid; e < 1024; e += 256) {
        const int row = e >> 4, c4 = e & 15;
        const int r = tile * 64 + row, m = r >> 8, n = r & 255;
        float4 xv = *(const float4*)(x + ((size_t)(b * SEQ + l + m) * NNODE + n) * FDIM + c4 * 4);
        *(__half2*)(xh + row * 72 + c4 * 4)     = __floats2half2_rn(xv.x, xv.y);
        *(__half2*)(xh + row * 72 + c4 * 4 + 2) = __floats2half2_rn(xv.z, xv.w);
        float4 wv = *(const float4*)(w2 + row * 64 + c4 * 4);
        *(__half2*)(wh + row * 72 + c4 * 4)     = __floats2half2_rn(wv.x, wv.y);
        *(__half2*)(wh + row * 72 + c4 * 4 + 2) = __floats2half2_rn(wv.z, wv.w);
    }
    __syncthreads();

    const int w = tid >> 5, lane = tid & 31;
    const int band = w >> 1, colg = w & 1;
    const int lq = lane >> 2, lr = lane & 3;
    float acc[4][4];
#pragma unroll
    for (int t = 0; t < 4; t++) { acc[t][0] = acc[t][1] = acc[t][2] = acc[t][3] = 0.f; }
#pragma unroll
    for (int ks = 0; ks < 4; ks++) {
        const int k0 = ks * 16;
        unsigned a0, a1, a2, a3; ldsm4h(a0, a1, a2, a3, xh, band * 16, k0, 72);
#pragma unroll
        for (int tt = 0; tt < 2; tt++) {
            unsigned b0, b1, b2v, b3v;
            ldsm4h_n(b0, b1, b2v, b3v, wh, colg * 32 + tt * 16, k0, 72);
            mma_f16(acc[tt * 2],     a0, a1, a2, a3, b0, b1);
            mma_f16(acc[tt * 2 + 1], a0, a1, a2, a3, b2v, b3v);
        }
    }
    const size_t ob = ((size_t)batch * N1 + tile * 64 + band * 16 + lq) * 64;
#pragma unroll
    for (int t = 0; t < 4; t++) {
        const int c = colg * 32 + t * 8 + lr * 2;
        const float bb0 = __ldg(b2 + c), bb1 = __ldg(b2 + c + 1);
        *(__half2*)(g_nfh + ob + c) = __floats2half2_rn(acc[t][0] + bb0, acc[t][1] + bb1);
        *(__half2*)(g_nfh + ob + (size_t)8 * 64 + c) = __floats2half2_rn(acc[t][2] + bb0, acc[t][3] + bb1);
    }
}

// ---------------- BN stats (streaming, half sources) --------------------------
__global__ void k_stats_p1(int which) {
    const int batch = blockIdx.x, tid = threadIdx.x;
    const int c = tid & 63, rg = tid >> 6;
    const __half* p = ((which == 0) ? g_nfh : g_oph) + (size_t)batch * N1 * 64;
    float s = 0.f, q = 0.f;
    for (int r = rg * 128; r < rg * 128 + 128; r++) {
        float v = __half2float(p[(size_t)r * 64 + c]);
        s += v; q += v * v;
    }
    __shared__ float sm[256], qm[256];
    sm[tid] = s; qm[tid] = q;
    __syncthreads();
    if (tid < 64) {
        g_part[which][batch][tid]      = sm[tid] + sm[tid + 64] + sm[tid + 128] + sm[tid + 192];
        g_part[which][batch][tid + 64] = qm[tid] + qm[tid + 64] + qm[tid + 128] + qm[tid + 192];
    }
}
__global__ void k_stats_p2(const float* __restrict__ w, const float* __restrict__ bb, int which) {
    const int c = threadIdx.x;
    float s = 0.f, q = 0.f;
    for (int b2 = 0; b2 < BP; b2++) { s += g_part[which][b2][c]; q += g_part[which][b2][c + 64]; }
    const float mu  = s / (float)NTOT;
    const float var = q / (float)NTOT - mu * mu;
    const float a   = w[c] * rsqrtf(var + 1e-5f);
    g_coef[which][0][c] = a;
    g_coef[which][1][c] = bb[c] - mu * a;
}

// ---------------- K1b: BN0 coefs + theta fold, fused (1 CTA, 128 thr) --------
__global__ void k_p2prep(const float* __restrict__ bn0w, const float* __restrict__ bn0b,
                         const float* __restrict__ th0w, const float* __restrict__ th1w) {
    __shared__ float ca[64], cd[64];
    const int tid = threadIdx.x;    // 128
    if (tid < 64) {
        float s = 0.f, q = 0.f;
        for (int b2 = 0; b2 < BP; b2++) { s += g_part[0][b2][tid]; q += g_part[0][b2][tid + 64]; }
        const float mu  = s / (float)NTOT;
        const float var = q / (float)NTOT - mu * mu;
        const float a   = bn0w[tid] * rsqrtf(var + 1e-5f);
        ca[tid] = a; cd[tid] = bn0b[tid] - mu * a;
    }
    __syncthreads();
    const int n = tid;
    const float* wr = (n < 64) ? (th0w + n * 64) : (th1w + (n - 64) * 64);
    float c = 0.f;
#pragma unroll 8
    for (int k = 0; k < 64; k++) {
        const float wv = wr[k];
        g_Wh[n * 64 + k] = __float2half(wv * ca[k]);
        c += wv * cd[k];
    }
    g_cbuf[n] = c;
}

// ---------------- K3: adj (softmax) + z1 fold + y=adj@nf + t = y@th1'^T ------
// smem bytes: nf_s[512*72]h @0 (reused: y_s head / Wh1 at +4608B)
//             adj_s[32*520]h @73728 (Wh0 aliases head)
//             reds[32*8]f @107008 | cbuf_s[128]f @108032 | rowsum_s[32]f @108544
__global__ void __launch_bounds__(512, 2) k_adj() {
    extern __shared__ char sraw[];
    __half* nf_s  = (__half*)sraw;
    __half* adj_s = (__half*)(sraw + 73728);
    __half* Wh0   = adj_s;                     // consumed before softmax writes
    float*  reds  = (float*)(sraw + 107008);
    float*  cbuf_s= (float*)(sraw + 108032);
    float*  rowsum_s = (float*)(sraw + 108544);
    const int tile = blockIdx.x, batch = blockIdx.y, tid = threadIdx.x;

    const __half* nfg = g_nfh + (size_t)batch * N1 * 64;
    for (int e = tid; e < 4096; e += 512)
        cp16(sptr(nf_s + (e >> 3) * 72 + (e & 7) * 8), nfg + e * 8);
    for (int e = tid; e < 512; e += 512)
        cp16(sptr(Wh0 + (e >> 3) * 72 + (e & 7) * 8), g_Wh + e * 8);
    if (tid < 32) cp16(sptr(cbuf_s + tid * 4), g_cbuf + tid * 4);
    CP_COMMIT; CP_WAIT0;
    __syncthreads();

    const int w = tid >> 5, lane = tid & 31;
    const int band = w >> 3, colg = w & 7;
    const int lq = lane >> 2, lr = lane & 3;
    const int rl0 = band * 16 + lq;
    const int rg0 = tile * 32 + rl0, rg1 = rg0 + 8;
    const int n0 = colg * 8;

    // ---- scores (32x512) + z1 fold (va = nf@th0' for this tile's rows) ----
    float acc[8][4];
#pragma unroll
    for (int t = 0; t < 8; t++) { acc[t][0] = acc[t][1] = acc[t][2] = acc[t][3] = 0.f; }
    float va[4] = {0.f, 0.f, 0.f, 0.f};
#pragma unroll
    for (int ks = 0; ks < 4; ks++) {
        const int k0 = ks * 16;
        unsigned a0, a1, a2, a3; ldsm4h(a0, a1, a2, a3, nf_s, tile * 32 + band * 16, k0, 72);
#pragma unroll
        for (int tt = 0; tt < 4; tt++) {
            unsigned b0, b1, b2v, b3v;
            ldsm4h_n(b0, b1, b2v, b3v, nf_s, colg * 64 + tt * 16, k0, 72);
            mma_f16(acc[tt * 2],     a0, a1, a2, a3, b0, b1);
            mma_f16(acc[tt * 2 + 1], a0, a1, a2, a3, b2v, b3v);
        }
        unsigned z0, z1; ldsm2h_n(z0, z1, Wh0, n0, k0, 72);
        mma_f16(va, a0, a1, a2, a3, z0, z1);
    }
    __syncthreads();   // scores/zfold done reading nf_s & Wh0

    // ---- leaky + exp + partial sums ----
    float s0 = 0.f, s1 = 0.f;
#pragma unroll
    for (int t = 0; t < 8; t++) {
#pragma unroll
        for (int j = 0; j < 2; j++) {
            const int col = colg * 64 + t * 8 + lr * 2 + j;
            float v = acc[t][j];
            if (col == rg0) v -= 1e8f;
            v = v > 0.f ? v : SLOPE * v;
            float e0 = __expf(v); acc[t][j] = e0; s0 += e0;
            float u = acc[t][2 + j];
            if (col == rg1) u -= 1e8f;
            u = u > 0.f ? u : SLOPE * u;
            float e1 = __expf(u); acc[t][2 + j] = e1; s1 += e1;
        }
    }
    s0 += __shfl_xor_sync(~0u, s0, 1); s0 += __shfl_xor_sync(~0u, s0, 2);
    s1 += __shfl_xor_sync(~0u, s1, 1); s1 += __shfl_xor_sync(~0u, s1, 2);
    if (lr == 0) { reds[rl0 * 8 + colg] = s0; reds[(rl0 + 8) * 8 + colg] = s1; }
    __syncthreads();
    float lo0 = 0.f, hi0 = 0.f, lo1 = 0.f, hi1 = 0.f;
#pragma unroll
    for (int c = 0; c < 4; c++) {
        lo0 += reds[rl0 * 8 + c];       hi0 += reds[rl0 * 8 + 4 + c];
        lo1 += reds[(rl0 + 8) * 8 + c]; hi1 += reds[(rl0 + 8) * 8 + 4 + c];
    }
    const float inv0 = 1.f / (lo0 + hi0), inv1 = 1.f / (lo1 + hi1);
    const bool rlo = (tile < 8);
    if (colg == 0 && lr == 0) {
        rowsum_s[rl0]     = (rlo ? lo0 + 0.7f * hi0 : 0.7f * lo0 + hi0) * inv0 + 1.f;
        rowsum_s[rl0 + 8] = (rlo ? lo1 + 0.7f * hi1 : 0.7f * lo1 + hi1) * inv1 + 1.f;
    }
    const float msk = (rlo != (colg < 4)) ? 0.7f : 1.0f;

    // ---- normalize + eye + mask -> adj_s via stmatrix (4 STSM.x4 per warp) ----
#pragma unroll
    for (int tp = 0; tp < 4; tp++) {
        const int ct = colg * 64 + tp * 16;
        const int cA0 = ct + lr * 2;
        const int cA1 = ct + 8 + lr * 2;
        float v0 = acc[2*tp][0] * inv0;     if (cA0     == rg0) v0 += 1.f;
        float v1 = acc[2*tp][1] * inv0;     if (cA0 + 1 == rg0) v1 += 1.f;
        float u0 = acc[2*tp][2] * inv1;     if (cA0     == rg1) u0 += 1.f;
        float u1 = acc[2*tp][3] * inv1;     if (cA0 + 1 == rg1) u1 += 1.f;
        float w0 = acc[2*tp+1][0] * inv0;   if (cA1     == rg0) w0 += 1.f;
        float w1 = acc[2*tp+1][1] * inv0;   if (cA1 + 1 == rg0) w1 += 1.f;
        float x0 = acc[2*tp+1][2] * inv1;   if (cA1     == rg1) x0 += 1.f;
        float x1 = acc[2*tp+1][3] * inv1;   if (cA1 + 1 == rg1) x1 += 1.f;
        stsm4h(adj_s, band * 16, ct, 520,
               h2u(v0 * msk, v1 * msk), h2u(u0 * msk, u1 * msk),
               h2u(w0 * msk, w1 * msk), h2u(x0 * msk, x1 * msk));
    }
    __syncthreads();

    // ---- split: warps 0-7 compute y = adj @ nf (16x16 tiles);
    //      warps 8-15 copy adj tile -> global ----
    float vyA[4] = {0.f, 0.f, 0.f, 0.f}, vyB[4] = {0.f, 0.f, 0.f, 0.f};
    int yband = 0, ycol = 0;
    if (w < 8) {
        yband = w >> 2;            // 0..1  (rows yband*16)
        ycol  = (w & 3) * 16;      // 0,16,32,48
#pragma unroll 4
        for (int ks = 0; ks < 32; ks += 2) {
            const int k0 = ks * 16;
            unsigned a0, a1, a2, a3; ldsm4h(a0, a1, a2, a3, adj_s, yband * 16, k0, 520);
            unsigned c0, c1, c2, c3; ldsm4h(c0, c1, c2, c3, adj_s, yband * 16, k0 + 16, 520);
            unsigned b0, b1, b2v, b3v; ldsm4h_t(b0, b1, b2v, b3v, nf_s, k0, ycol, 72);
            unsigned d0, d1, d2v, d3v; ldsm4h_t(d0, d1, d2v, d3v, nf_s, k0, ycol + 8, 72);
            mma_f16(vyA, a0, a1, a2, a3, b0, b1);
            mma_f16(vyA, c0, c1, c2, c3, b2v, b3v);
            mma_f16(vyB, a0, a1, a2, a3, d0, d1);
            mma_f16(vyB, c0, c1, c2, c3, d2v, d3v);
        }
    } else {
        const size_t gb = ((size_t)batch * N1 + tile * 32) * N1;
        for (int e = tid - 256; e < 2048; e += 256) {
            const int r = e >> 6, c8 = e & 63;
            *(uint4*)(g_adjh + gb + (size_t)r * N1 + c8 * 8) =
                *(const uint4*)(adj_s + r * 520 + c8 * 8);
        }
    }
    __syncthreads();   // y-phase done reading nf_s; copy done

    // ---- stage y into nf_s head (stmatrix); fetch th1' into nf_s+4608B ----
    __half* y_s  = nf_s;
    __half* Wh1s = nf_s + 2304;
    if (w < 8) {
        stsm4h(y_s, yband * 16, ycol, 72,
               h2u(vyA[0], vyA[1]), h2u(vyA[2], vyA[3]),
               h2u(vyB[0], vyB[1]), h2u(vyB[2], vyB[3]));
    }
    for (int e = tid; e < 512; e += 512)
        cp16(sptr(Wh1s + (e >> 3) * 72 + (e & 7) * 8), g_Wh + 64 * 64 + e * 8);
    CP_COMMIT; CP_WAIT0;
    __syncthreads();

    // ---- t = va + y@th1'^T + rowsum*c1 + c0 ----
    float at[4] = {0.f, 0.f, 0.f, 0.f};
#pragma unroll
    for (int ks = 0; ks < 4; ks++) {
        const int k0 = ks * 16;
        unsigned a0, a1, a2, a3; ldsm4h(a0, a1, a2, a3, y_s, band * 16, k0, 72);
        unsigned b0, b1; ldsm2h_n(b0, b1, Wh1s, n0, k0, 72);
        mma_f16(at, a0, a1, a2, a3, b0, b1);
    }
    const size_t rb = (size_t)batch * N1 + tile * 32 + rl0;
    const int cA = n0 + lr * 2;
    const float c0a = cbuf_s[cA], c0b = cbuf_s[cA + 1];
    const float c1a = cbuf_s[64 + cA], c1b = cbuf_s[64 + cA + 1];
    const float rs0 = rowsum_s[rl0], rs1 = rowsum_s[rl0 + 8];
    *(__half2*)(g_th + rb * 64 + cA) =
        __floats2half2_rn(va[0] + at[0] + rs0 * c1a + c0a,
                          va[1] + at[1] + rs0 * c1b + c0b);
    *(__half2*)(g_th + (rb + 8) * 64 + cA) =
        __floats2half2_rn(va[2] + at[2] + rs1 * c1a + c0a,
                          va[3] + at[3] + rs1 * c1b + c0b);
}

// ---------------- K4: op = adj @ t + (th0b+th1b), 128-row tiles --------------
// smem bytes: t_s[512*72]h @0 | cbA[128*72]h @73728 | cbB @92160
__global__ void __launch_bounds__(512, 2) k_out(const float* __restrict__ th0b,
                                                const float* __restrict__ th1b) {
    extern __shared__ char sraw[];
    __half* t_s = (__half*)sraw;
    __half* cbA = (__half*)(sraw + 73728);
    __half* cbB = (__half*)(sraw + 92160);
    const int tile = blockIdx.x, batch = blockIdx.y, tid = threadIdx.x;

    const __half* tg = g_th + (size_t)batch * N1 * 64;
    const __half* ag = g_adjh + ((size_t)batch * N1 + tile * 128) * N1;
    for (int e = tid; e < 4096; e += 512)
        cp16(sptr(t_s + (e >> 3) * 72 + (e & 7) * 8), tg + e * 8);
    for (int e = tid; e < 1024; e += 512) {
        const int r = e >> 3, c8 = e & 7;
        cp16(sptr(cbA + r * 72 + c8 * 8), ag + (size_t)r * N1 + c8 * 8);
    }
    CP_COMMIT;

    const int w = tid >> 5, lane = tid & 31;
    const int band = w >> 1, colg = w & 1;        // 8 row-bands x 2 col-groups
    const int lq = lane >> 2, lr = lane & 3;
    float acc[4][4];
#pragma unroll
    for (int t = 0; t < 4; t++) { acc[t][0] = acc[t][1] = acc[t][2] = acc[t][3] = 0.f; }

    for (int ch = 0; ch < 8; ch++) {
        __half* cb = (ch & 1) ? cbB : cbA;
        if (ch < 7) {
            __half* nb = (ch & 1) ? cbA : cbB;
            for (int e = tid; e < 1024; e += 512) {
                const int r = e >> 3, c8 = e & 7;
                cp16(sptr(nb + r * 72 + c8 * 8), ag + (size_t)r * N1 + (ch + 1) * 64 + c8 * 8);
            }
            CP_COMMIT; CP_WAIT1;
        } else {
            CP_WAIT0;
        }
        __syncthreads();
#pragma unroll
        for (int kp = 0; kp < 64; kp += 32) {
            unsigned a0, a1, a2, a3; ldsm4h(a0, a1, a2, a3, cb, band * 16, kp, 72);
            unsigned c0, c1, c2, c3; ldsm4h(c0, c1, c2, c3, cb, band * 16, kp + 16, 72);
#pragma unroll
            for (int nt = 0; nt < 4; nt++) {
                unsigned b0, b1, b2v, b3v;
                ldsm4h_t(b0, b1, b2v, b3v, t_s, ch * 64 + kp, colg * 32 + nt * 8, 72);
                mma_f16(acc[nt], a0, a1, a2, a3, b0, b1);
                mma_f16(acc[nt], c0, c1, c2, c3, b2v, b3v);
            }
        }
        __syncthreads();
    }
    const size_t rb = (size_t)batch * N1 + tile * 128 + band * 16 + lq;
#pragma unroll
    for (int nt = 0; nt < 4; nt++) {
        const int cA = colg * 32 + nt * 8 + lr * 2;
        const float bc0 = __ldg(th0b + cA) + __ldg(th1b + cA);
        const float bc1 = __ldg(th0b + cA + 1) + __ldg(th1b + cA + 1);
        *(__half2*)(g_oph + rb * 64 + cA) = __floats2half2_rn(acc[nt][0] + bc0, acc[nt][1] + bc1);
        *(__half2*)(g_oph + (rb + 8) * 64 + cA) = __floats2half2_rn(acc[nt][2] + bc0, acc[nt][3] + bc1);
    }
}

// ---------------- K5: BN1 affine + leaky + mean pool (half2 reads) -----------
__global__ void k_final(float* __restrict__ out) {
    const int idx = blockIdx.x * 256 + threadIdx.x;
    const int c2 = idx & 31;
    const int n = (idx >> 5) & 255;
    const int b = idx >> 13;
    const float a0 = g_coef[1][0][c2 * 2], a1 = g_coef[1][0][c2 * 2 + 1];
    const float d0 = g_coef[1][1][c2 * 2], d1 = g_coef[1][1][c2 * 2 + 1];
    float s0 = 0.f, s1 = 0.f;
#pragma unroll 2
    for (int l = 0; l < LWIN; l++)
#pragma unroll
        for (int m = 0; m < 2; m++) {
            __half2 h = *(const __half2*)(g_oph +
                (((size_t)(b * LWIN + l) * N1 + m * NNODE + n) << 6) + c2 * 2);
            float2 f = __half22float2(h);
            float v0 = a0 * f.x + d0; s0 += (v0 > 0.f) ? v0 : SLOPE * v0;
            float v1 = a1 * f.y + d1; s1 += (v1 > 0.f) ? v1 : SLOPE * v1;
        }
    *(float2*)(out + (((size_t)(b * NNODE + n)) << 6) + c2 * 2) =
        make_float2(s0 * (1.f / 32.f), s1 * (1.f / 32.f));
}

// ---------------- launch ------------------------------------------------------
extern "C" void kernel_launch(void* const* d_in, const int* in_sizes, int n_in,
                              void* d_out, int out_size) {
    const float* x    = (const float*)d_in[0];
    const float* w2   = (const float*)d_in[1];
    const float* b2   = (const float*)d_in[2];
    const float* bn0w = (const float*)d_in[3];
    const float* bn0b = (const float*)d_in[4];
    const float* th0w = (const float*)d_in[5];
    const float* th0b = (const float*)d_in[6];
    const float* th1w = (const float*)d_in[7];
    const float* th1b = (const float*)d_in[8];
    const float* bn1w = (const float*)d_in[9];
    const float* bn1b = (const float*)d_in[10];
    float* out = (float*)d_out;

    const int SMEM_ADJ = 108672;
    const int SMEM_OUT = 110592;
    cudaFuncSetAttribute(k_adj, cudaFuncAttributeMaxDynamicSharedMemorySize, SMEM_ADJ);
    cudaFuncSetAttribute(k_out, cudaFuncAttributeMaxDynamicSharedMemorySize, SMEM_OUT);

    k_nf<<<dim3(8, BP), 256>>>(x, w2, b2);
    k_stats_p1<<<BP, 256>>>(0);
    k_p2prep<<<1, 128>>>(bn0w, bn0b, th0w, th1w);
    k_adj<<<dim3(16, BP), 512, SMEM_ADJ>>>();
    k_out<<<dim3(4, BP), 512, SMEM_OUT>>>(th0b, th1b);
    k_stats_p1<<<BP, 256>>>(1);
    k_stats_p2<<<1, 64>>>(bn1w, bn1b, 1);
    k_final<<<512, 256>>>(out);
}